// round 11
// baseline (speedup 1.0000x reference)
#include <cuda_runtime.h>
#include <math.h>
#include <stdint.h>

#define TT 4096
#define NB 8
#define NBT (NB*TT)

__device__ __align__(256) float g_s1[NB*208*TT];
__device__ __align__(256) float g_s2[NB*160*TT];
__device__ __align__(256) float g_x [NBT*64];
__device__ __align__(256) float g_q [NBT*64];
__device__ __align__(256) float g_k [NBT*64];
__device__ __align__(256) float g_v [NBT*64];

__device__ __forceinline__ uint32_t f2tf32(float x){
    uint32_t r; asm("cvt.rna.tf32.f32 %0, %1;" : "=r"(r) : "f"(x)); return r;
}
__device__ __forceinline__ uint2 splitf(float x){
    uint32_t h = f2tf32(x);
    return make_uint2(h, f2tf32(x - __uint_as_float(h)));
}

#define MMA_TF32(d, a0,a1,a2,a3, b0,b1) \
  asm volatile("mma.sync.aligned.m16n8k8.row.col.f32.tf32.tf32.f32 " \
      "{%0,%1,%2,%3}, {%4,%5,%6,%7}, {%8,%9}, {%0,%1,%2,%3};" \
      : "+f"(d[0]), "+f"(d[1]), "+f"(d[2]), "+f"(d[3]) \
      : "r"(a0), "r"(a1), "r"(a2), "r"(a3), "r"(b0), "r"(b1))

// ============ stage 1: causal conv (1x3) + maxpool3(freq) + relu ============
__global__ void k_s1(const float* __restrict__ spec, const float* __restrict__ w,
                     const float* __restrict__ bias){
    int id = blockIdx.x*256 + threadIdx.x;
    int t  = id & (TT-1);
    int r  = id >> 12;
    int f2 = r % 26, b = r / 26;
    const float* sp = spec + (size_t)(b*81 + f2*3)*TT + t;
    float s[5][3];
    #pragma unroll
    for (int j=0;j<5;j++)
        #pragma unroll
        for (int i=0;i<3;i++)
            s[j][i] = (t+i < TT) ? sp[j*TT+i] : 0.f;
    #pragma unroll
    for (int c=0;c<8;c++){
        float a0=0.f,a1=0.f,a2=0.f;
        #pragma unroll
        for (int i=0;i<3;i++){
            if (t+i < TT){
                float w0=__ldg(w+(i*8+c)*3+0), w1=__ldg(w+(i*8+c)*3+1), w2=__ldg(w+(i*8+c)*3+2);
                float bb=__ldg(bias+i*8+c);
                a0 += bb + w0*s[0][i]+w1*s[1][i]+w2*s[2][i];
                a1 += bb + w0*s[1][i]+w1*s[2][i]+w2*s[3][i];
                a2 += bb + w0*s[2][i]+w1*s[3][i]+w2*s[4][i];
            }
        }
        float m = fmaxf(fmaxf(a0,a1),a2);
        g_s1[((size_t)(b*8+c)*26+f2)*TT + t] = fmaxf(m, 0.f);
    }
}

// ============ stage 2: conv (1x12) + maxpool3 + relu ============
__global__ void k_s2(const float* __restrict__ w2, const float* __restrict__ b2){
    extern __shared__ float sm[];
    float* s1s = sm;            // [208][64]
    float* ws  = sm + 208*64;   // 3072
    int tid = threadIdx.x, b = blockIdx.y, t0 = blockIdx.x*64;
    for (int i=tid; i<208*64; i+=256){
        int tl = i & 63, fr = i >> 6;
        s1s[i] = g_s1[((size_t)(b*208+fr))*TT + t0 + tl];
    }
    for (int i=tid; i<3072; i+=256) ws[i] = w2[i];
    __syncthreads();
    int tl = tid & 63, g = tid >> 6;
    for (int cb=0; cb<2; cb++){
        int co0 = g*8 + cb*4;
        float acc[4][5][3];
        #pragma unroll
        for (int u=0;u<4;u++){
            float bb = __ldg(b2 + co0 + u);
            #pragma unroll
            for (int f2=0;f2<5;f2++){ acc[u][f2][0]=bb; acc[u][f2][1]=bb; acc[u][f2][2]=bb; }
        }
        for (int cin=0; cin<8; cin++){
            float sv[26];
            #pragma unroll
            for (int ff=0; ff<26; ff++) sv[ff] = s1s[(cin*26+ff)*64 + tl];
            float w[4][12];
            #pragma unroll
            for (int u=0;u<4;u++)
                #pragma unroll
                for (int k=0;k<12;k++) w[u][k] = ws[(co0+u)*96 + cin*12 + k];
            #pragma unroll
            for (int f2=0; f2<5; f2++)
                #pragma unroll
                for (int k=0;k<12;k++)
                    #pragma unroll
                    for (int u=0;u<4;u++){
                        float wk = w[u][k];
                        acc[u][f2][0] += wk*sv[f2*3+k+0];
                        acc[u][f2][1] += wk*sv[f2*3+k+1];
                        acc[u][f2][2] += wk*sv[f2*3+k+2];
                    }
        }
        #pragma unroll
        for (int u=0;u<4;u++)
            #pragma unroll
            for (int f2=0;f2<5;f2++){
                float m = fmaxf(fmaxf(acc[u][f2][0],acc[u][f2][1]),acc[u][f2][2]);
                g_s2[((size_t)((b*32+co0+u)*5+f2))*TT + t0 + tl] = fmaxf(m, 0.f);
            }
    }
}

// ============ stage 3: causal conv (1x3, cin32,co64) + maxpool3 + relu ============
__global__ void __launch_bounds__(512) k_s3(const float* __restrict__ w3, const float* __restrict__ b3){
    extern __shared__ float sm[];
    float* s2s = sm;              // [160][132]
    float* w3s = sm + 160*132;    // 18432
    int tid = threadIdx.x, b = blockIdx.y, t0 = blockIdx.x*128;
    for (int i=tid; i<160*132; i+=512){
        int tl = i % 132, fr = i / 132;
        int tg = t0 + tl;
        s2s[i] = (tg < TT && tl < 130) ? g_s2[((size_t)(b*160+fr))*TT + tg] : 0.f;
    }
    for (int i=tid; i<18432; i+=512){
        int co = i & 63, r = i >> 6;
        int k = r % 3; r /= 3;
        int cin = r & 31, ii = r >> 5;
        w3s[i] = w3[((size_t)(ii*64+co)*32+cin)*3 + k];
    }
    __syncthreads();
    int co = tid & 63, tg8 = tid >> 6;
    float bb0 = __ldg(b3+co), bb1 = __ldg(b3+64+co), bb2 = __ldg(b3+128+co);
    for (int chunk=0; chunk<2; chunk++){
        int tlbase = tg8*16 + chunk*8;
        float acc[8][3];
        #pragma unroll
        for (int rr=0;rr<8;rr++){ acc[rr][0]=0.f; acc[rr][1]=0.f; acc[rr][2]=0.f; }
        for (int cin=0; cin<32; cin++){
            float sv[5][12];
            #pragma unroll
            for (int ff=0; ff<5; ff++){
                const float4* p = (const float4*)(s2s + (cin*5+ff)*132 + tlbase);
                float4 u0=p[0], u1=p[1], u2=p[2];
                sv[ff][0]=u0.x; sv[ff][1]=u0.y; sv[ff][2]=u0.z; sv[ff][3]=u0.w;
                sv[ff][4]=u1.x; sv[ff][5]=u1.y; sv[ff][6]=u1.z; sv[ff][7]=u1.w;
                sv[ff][8]=u2.x; sv[ff][9]=u2.y; sv[ff][10]=u2.z; sv[ff][11]=u2.w;
            }
            #pragma unroll
            for (int ii=0; ii<3; ii++)
                #pragma unroll
                for (int k=0; k<3; k++){
                    float wk = w3s[((ii*32+cin)*3+k)*64 + co];
                    #pragma unroll
                    for (int f=0; f<3; f++)
                        #pragma unroll
                        for (int rr=0; rr<8; rr++)
                            acc[rr][f] += wk*sv[f+k][rr+ii];
                }
        }
        #pragma unroll
        for (int rr=0; rr<8; rr++){
            int tg = t0 + tlbase + rr;
            float a0=acc[rr][0]+bb0, a1=acc[rr][1]+bb0, a2=acc[rr][2]+bb0;
            if (tg+1 < TT){ a0+=bb1; a1+=bb1; a2+=bb1; }
            if (tg+2 < TT){ a0+=bb2; a1+=bb2; a2+=bb2; }
            float m = fmaxf(fmaxf(a0,a1),a2);
            g_x[((size_t)(b*TT+tg))*64 + co] = fmaxf(m, 0.f);
        }
    }
}

// ============ LN1 + QKV via 3xTF32 mma (128 tok/block, packed hi/lo, 4x4 warp grid) ============
// SMEM: Wp uint2[64][196] ([Wq|Wk|Wv], hi/lo), Ha uint2[128][68], bs[192]
__global__ void __launch_bounds__(512) k_qkv(
        const float* __restrict__ Wq, const float* __restrict__ bq,
        const float* __restrict__ Wk, const float* __restrict__ bk,
        const float* __restrict__ Wv, const float* __restrict__ bv,
        const float* __restrict__ gam, const float* __restrict__ bet){
    extern __shared__ char smraw[];
    uint2* Wp = (uint2*)smraw;            // 64*196
    uint2* Ha = Wp + 64*196;              // 128*68
    float* bs = (float*)(Ha + 128*68);    // 192
    int tid = threadIdx.x;

    for (int i=tid; i<4096; i+=512){
        int col = i >> 6, d = i & 63;
        Wp[d*196+col]     = splitf(Wq[i]);
        Wp[d*196+64+col]  = splitf(Wk[i]);
        Wp[d*196+128+col] = splitf(Wv[i]);
    }
    if (tid < 64){ bs[tid]=bq[tid]; bs[64+tid]=bk[tid]; bs[128+tid]=bv[tid]; }

    // LN1: 4 threads/token, 16 dims each
    {
        int tok = tid >> 2, lane4 = tid & 3;
        int gtok = blockIdx.x*128 + tok;
        const float* xr = g_x + (size_t)gtok*64 + lane4*16;
        float v[16];
        #pragma unroll
        for (int c=0;c<4;c++){
            float4 u = *(const float4*)(xr + c*4);
            v[c*4]=u.x; v[c*4+1]=u.y; v[c*4+2]=u.z; v[c*4+3]=u.w;
        }
        float s=0.f, ss=0.f;
        #pragma unroll
        for (int m=0;m<16;m++){ s += v[m]; ss += v[m]*v[m]; }
        s += __shfl_xor_sync(0xffffffffu,s,1); ss += __shfl_xor_sync(0xffffffffu,ss,1);
        s += __shfl_xor_sync(0xffffffffu,s,2); ss += __shfl_xor_sync(0xffffffffu,ss,2);
        float mean = s*(1.f/64.f);
        float var  = ss*(1.f/64.f) - mean*mean;
        float rstd = rsqrtf(fmaxf(var,0.f) + 1e-5f);
        #pragma unroll
        for (int m=0;m<16;m++){
            int dd = lane4*16+m;
            Ha[tok*68+dd] = splitf((v[m]-mean)*rstd*__ldg(gam+dd) + __ldg(bet+dd));
        }
    }
    __syncthreads();

    // 16 warps = 4 m-groups (32 rows) x 4 n-groups (48 cols)
    int lane = tid & 31, w = tid >> 5;
    int m0 = (w >> 2) << 5;
    int n0 = (w & 3) * 48;
    float acc[2][6][4];
    #pragma unroll
    for (int mt=0;mt<2;mt++)
        #pragma unroll
        for (int nt=0;nt<6;nt++){ acc[mt][nt][0]=0.f; acc[mt][nt][1]=0.f; acc[mt][nt][2]=0.f; acc[mt][nt][3]=0.f; }
    int r0 = m0 + (lane>>2);
    #pragma unroll
    for (int kt=0; kt<8; kt++){
        int k0 = kt*8;
        uint2 af[2][4];
        #pragma unroll
        for (int mt=0; mt<2; mt++){
            int ai = (r0+mt*16)*68 + k0 + (lane&3);
            af[mt][0]=Ha[ai]; af[mt][1]=Ha[ai+544]; af[mt][2]=Ha[ai+4]; af[mt][3]=Ha[ai+548];
        }
        int bi = (k0+(lane&3))*196 + n0 + (lane>>2);
        #pragma unroll
        for (int nt=0; nt<6; nt++){
            uint2 b0 = Wp[bi+nt*8], b1 = Wp[bi+nt*8+784];
            #pragma unroll
            for (int mt=0; mt<2; mt++){
                MMA_TF32(acc[mt][nt], af[mt][0].y,af[mt][1].y,af[mt][2].y,af[mt][3].y, b0.x,b1.x);
                MMA_TF32(acc[mt][nt], af[mt][0].x,af[mt][1].x,af[mt][2].x,af[mt][3].x, b0.y,b1.y);
                MMA_TF32(acc[mt][nt], af[mt][0].x,af[mt][1].x,af[mt][2].x,af[mt][3].x, b0.x,b1.x);
            }
        }
    }
    #pragma unroll
    for (int mt=0; mt<2; mt++){
        int gt = blockIdx.x*128 + m0 + mt*16 + (lane>>2);
        #pragma unroll
        for (int nt=0; nt<6; nt++){
            int colg = n0 + nt*8 + 2*(lane&3);
            int seg = colg >> 6, cl = colg & 63;
            float* dst = (seg==0) ? g_q : (seg==1) ? g_k : g_v;
            float b0 = bs[colg], b1 = bs[colg+1];
            float2 v0; v0.x = acc[mt][nt][0] + b0; v0.y = acc[mt][nt][1] + b1;
            *(float2*)(dst + (size_t)gt*64 + cl) = v0;
            float2 v1; v1.x = acc[mt][nt][2] + b0; v1.y = acc[mt][nt][3] + b1;
            *(float2*)(dst + (size_t)(gt+8)*64 + cl) = v1;
        }
    }
}

// ============ attention + residual + LN2 + FF(3xTF32 mma) + residual (128 tok/block) ============
// SMEM: W1p uint2[64][68], W2p uint2[64][68], hsP uint2[128][68], xs float[128][68], bs[128]
__global__ void __launch_bounds__(512) k_attnff(
        const float* __restrict__ Er, int shift,
        const float* __restrict__ W1p_g, const float* __restrict__ b1p,
        const float* __restrict__ W2p_g, const float* __restrict__ b2p,
        const float* __restrict__ gam, const float* __restrict__ bet){
    extern __shared__ char smraw[];
    uint2* W1p = (uint2*)smraw;            // 64*68
    uint2* W2p = W1p + 64*68;              // 64*68
    uint2* hsP = W2p + 64*68;              // 128*68
    float* xs  = (float*)(hsP + 128*68);   // 128*68
    float* bs  = xs + 128*68;              // 128
    int tid = threadIdx.x;
    for (int i=tid; i<4096; i+=512){
        int col = i >> 6, d = i & 63;
        W1p[d*68+col] = splitf(W1p_g[i]);
        W2p[d*68+col] = splitf(W2p_g[i]);
    }
    if (tid < 64){ bs[tid]=b1p[tid]; bs[64+tid]=b2p[tid]; }

    // ---- attention: 4 threads/token, 2 heads each ----
    {
        int tok = tid >> 2, hp = (tid & 3)*2;
        int gtok = blockIdx.x*128 + tok;
        int b = gtok >> 12, t = gtok & (TT-1);
        size_t bt = (size_t)b*TT + t;
        int sh[6]; sh[0]=0; sh[1]=0; sh[2]=shift; sh[3]=2*shift; sh[4]=3*shift; sh[5]=4*shift;
        #pragma unroll
        for (int hh=0; hh<2; hh++){
            int h = hp + hh;
            const float* qp = g_q + bt*64 + h*8;
            float4 q0 = *(const float4*)qp, q1 = *(const float4*)(qp+4);
            float q[8] = {q0.x,q0.y,q0.z,q0.w,q1.x,q1.y,q1.z,q1.w};
            const float* er = Er + h*48;
            float lg[6];
            #pragma unroll
            for (int j=0;j<6;j++){
                float qe = 0.f;
                #pragma unroll
                for (int d=0;d<8;d++) qe += q[d]*__ldg(er + d*6 + j);
                lg[j] = qe;
            }
            #pragma unroll
            for (int j=0;j<6;j++){
                int tp = t - sh[j];
                float qk = 0.f;
                if (tp >= 0){
                    const float* kp = g_k + ((size_t)b*TT+tp)*64 + h*8;
                    float4 k0 = *(const float4*)kp, k1 = *(const float4*)(kp+4);
                    qk = q[0]*k0.x + q[1]*k0.y + q[2]*k0.z + q[3]*k0.w
                       + q[4]*k1.x + q[5]*k1.y + q[6]*k1.z + q[7]*k1.w;
                }
                lg[j] = (qk + lg[j]) * 0.3535533905932738f;
            }
            float mx = lg[0];
            #pragma unroll
            for (int j=1;j<6;j++) mx = fmaxf(mx, lg[j]);
            float e[6], se = 0.f;
            #pragma unroll
            for (int j=0;j<6;j++){ e[j] = expf(lg[j]-mx); se += e[j]; }
            float inv = 1.f/se;
            float o[8] = {0,0,0,0,0,0,0,0};
            #pragma unroll
            for (int j=0;j<6;j++){
                int tp = t - sh[j];
                if (tp >= 0){
                    const float* vp = g_v + ((size_t)b*TT+tp)*64 + h*8;
                    float4 v0 = *(const float4*)vp, v1 = *(const float4*)(vp+4);
                    float a = e[j];
                    o[0]+=a*v0.x; o[1]+=a*v0.y; o[2]+=a*v0.z; o[3]+=a*v0.w;
                    o[4]+=a*v1.x; o[5]+=a*v1.y; o[6]+=a*v1.z; o[7]+=a*v1.w;
                }
            }
            const float* xp = g_x + (size_t)gtok*64 + h*8;
            float4 x0 = *(const float4*)xp, x1 = *(const float4*)(xp+4);
            float* xd = xs + tok*68 + h*8;
            xd[0]=x0.x+o[0]*inv; xd[1]=x0.y+o[1]*inv; xd[2]=x0.z+o[2]*inv; xd[3]=x0.w+o[3]*inv;
            xd[4]=x1.x+o[4]*inv; xd[5]=x1.y+o[5]*inv; xd[6]=x1.z+o[6]*inv; xd[7]=x1.w+o[7]*inv;
        }
    }
    __syncthreads();

    // ---- LN2: 4 threads/token, write tf32 hi/lo ----
    {
        int tok = tid >> 2, lane4 = tid & 3;
        float v[16];
        #pragma unroll
        for (int m=0;m<16;m++) v[m] = xs[tok*68 + lane4*16 + m];
        float s=0.f, ss=0.f;
        #pragma unroll
        for (int m=0;m<16;m++){ s += v[m]; ss += v[m]*v[m]; }
        s += __shfl_xor_sync(0xffffffffu,s,1); ss += __shfl_xor_sync(0xffffffffu,ss,1);
        s += __shfl_xor_sync(0xffffffffu,s,2); ss += __shfl_xor_sync(0xffffffffu,ss,2);
        float mean = s*(1.f/64.f);
        float var  = ss*(1.f/64.f) - mean*mean;
        float rstd = rsqrtf(fmaxf(var,0.f) + 1e-5f);
        #pragma unroll
        for (int m=0;m<16;m++){
            int dd = lane4*16+m;
            hsP[tok*68+dd] = splitf((v[m]-mean)*rstd*__ldg(gam+dd) + __ldg(bet+dd));
        }
    }
    __syncthreads();

    // 16 warps = 8 m-groups (16 rows) x 2 n-groups (32 cols)
    int lane = tid & 31, w = tid >> 5;
    int m0 = (w >> 1) << 4;
    int n0 = (w & 1) * 32;
    int r0 = m0 + (lane>>2);

    // ---- GEMM1 (3xTF32) ----
    float acc[4][4];
    #pragma unroll
    for (int nt=0;nt<4;nt++){ acc[nt][0]=0.f; acc[nt][1]=0.f; acc[nt][2]=0.f; acc[nt][3]=0.f; }
    #pragma unroll
    for (int kt=0; kt<8; kt++){
        int k0 = kt*8;
        int ai = r0*68 + k0 + (lane&3);
        uint2 a0=hsP[ai], a1=hsP[ai+544], a2=hsP[ai+4], a3=hsP[ai+548];
        int bi = (k0+(lane&3))*68 + n0 + (lane>>2);
        #pragma unroll
        for (int nt=0; nt<4; nt++){
            uint2 b0 = W1p[bi+nt*8], b1 = W1p[bi+nt*8+272];
            MMA_TF32(acc[nt], a0.y,a1.y,a2.y,a3.y, b0.x,b1.x);
            MMA_TF32(acc[nt], a0.x,a1.x,a2.x,a3.x, b0.y,b1.y);
            MMA_TF32(acc[nt], a0.x,a1.x,a2.x,a3.x, b0.x,b1.x);
        }
    }
    __syncthreads();
    // gelu -> hsP (hi/lo)
    #pragma unroll
    for (int nt=0; nt<4; nt++){
        int colg = n0 + nt*8 + 2*(lane&3);
        float bb0 = bs[colg], bb1 = bs[colg+1];
        float z;
        z = acc[nt][0] + bb0; z = 0.5f*z*(1.f + erff(z*0.7071067811865475f)); hsP[r0*68 + colg]       = splitf(z);
        z = acc[nt][1] + bb1; z = 0.5f*z*(1.f + erff(z*0.7071067811865475f)); hsP[r0*68 + colg + 1]   = splitf(z);
        z = acc[nt][2] + bb0; z = 0.5f*z*(1.f + erff(z*0.7071067811865475f)); hsP[(r0+8)*68 + colg]   = splitf(z);
        z = acc[nt][3] + bb1; z = 0.5f*z*(1.f + erff(z*0.7071067811865475f)); hsP[(r0+8)*68 + colg+1] = splitf(z);
    }
    __syncthreads();

    // ---- GEMM2 (3xTF32) + residual ----
    float acc2[4][4];
    #pragma unroll
    for (int nt=0;nt<4;nt++){ acc2[nt][0]=0.f; acc2[nt][1]=0.f; acc2[nt][2]=0.f; acc2[nt][3]=0.f; }
    #pragma unroll
    for (int kt=0; kt<8; kt++){
        int k0 = kt*8;
        int ai = r0*68 + k0 + (lane&3);
        uint2 a0=hsP[ai], a1=hsP[ai+544], a2=hsP[ai+4], a3=hsP[ai+548];
        int bi = (k0+(lane&3))*68 + n0 + (lane>>2);
        #pragma unroll
        for (int nt=0; nt<4; nt++){
            uint2 b0 = W2p[bi+nt*8], b1 = W2p[bi+nt*8+272];
            MMA_TF32(acc2[nt], a0.y,a1.y,a2.y,a3.y, b0.x,b1.x);
            MMA_TF32(acc2[nt], a0.x,a1.x,a2.x,a3.x, b0.y,b1.y);
            MMA_TF32(acc2[nt], a0.x,a1.x,a2.x,a3.x, b0.x,b1.x);
        }
    }
    int gt = blockIdx.x*128 + r0;
    #pragma unroll
    for (int nt=0; nt<4; nt++){
        int colg = n0 + nt*8 + 2*(lane&3);
        float bb0 = bs[64+colg], bb1 = bs[64+colg+1];
        float2 v0;
        v0.x = xs[r0*68 + colg]     + acc2[nt][0] + bb0;
        v0.y = xs[r0*68 + colg + 1] + acc2[nt][1] + bb1;
        *(float2*)(g_x + (size_t)gt*64 + colg) = v0;
        float2 v1;
        v1.x = xs[(r0+8)*68 + colg]     + acc2[nt][2] + bb0;
        v1.y = xs[(r0+8)*68 + colg + 1] + acc2[nt][3] + bb1;
        *(float2*)(g_x + (size_t)(gt+8)*64 + colg) = v1;
    }
}

// ============ 1x1 conv out + sigmoid ============
__global__ void k_out(const float* __restrict__ ow, const float* __restrict__ ob,
                      float* __restrict__ out){
    int id = blockIdx.x*256 + threadIdx.x;
    int t = id & (TT-1), b = id >> 12;
    const float4* xp = (const float4*)(g_x + (size_t)id*64);
    float a0 = __ldg(ob), a1 = __ldg(ob+1);
    #pragma unroll
    for (int d4=0; d4<16; d4++){
        float4 xv = xp[d4];
        a0 += xv.x*__ldg(ow+d4*4) + xv.y*__ldg(ow+d4*4+1) + xv.z*__ldg(ow+d4*4+2) + xv.w*__ldg(ow+d4*4+3);
        a1 += xv.x*__ldg(ow+64+d4*4) + xv.y*__ldg(ow+64+d4*4+1) + xv.z*__ldg(ow+64+d4*4+2) + xv.w*__ldg(ow+64+d4*4+3);
    }
    out[((size_t)(b*2))*TT + t]   = 1.f/(1.f+expf(-a0));
    out[((size_t)(b*2+1))*TT + t] = 1.f/(1.f+expf(-a1));
}

extern "C" void kernel_launch(void* const* d_in, const int* in_sizes, int n_in,
                              void* d_out, int out_size){
    const float* spec = (const float*)d_in[0];
    const float* c1w = (const float*)d_in[1];
    const float* c1b = (const float*)d_in[2];
    const float* c2w = (const float*)d_in[3];
    const float* c2b = (const float*)d_in[4];
    const float* c3w = (const float*)d_in[5];
    const float* c3b = (const float*)d_in[6];
    const float* Wq  = (const float*)d_in[7];
    const float* bq  = (const float*)d_in[8];
    const float* Wk  = (const float*)d_in[9];
    const float* bk  = (const float*)d_in[10];
    const float* Wv  = (const float*)d_in[11];
    const float* bv  = (const float*)d_in[12];
    const float* Er  = (const float*)d_in[13];
    const float* g1  = (const float*)d_in[14];
    const float* be1 = (const float*)d_in[15];
    const float* W1  = (const float*)d_in[16];
    const float* b1  = (const float*)d_in[17];
    const float* W2  = (const float*)d_in[18];
    const float* b2  = (const float*)d_in[19];
    const float* g2  = (const float*)d_in[20];
    const float* be2 = (const float*)d_in[21];
    const float* ow  = (const float*)d_in[22];
    const float* ob  = (const float*)d_in[23];

    const int SM_QKV    = (64*196 + 128*68)*8 + 192*4;            // 170752
    const int SM_ATTNFF = (64*68*2 + 128*68)*8 + 128*68*4 + 512;  // 174592

    cudaFuncSetAttribute(k_s2,  cudaFuncAttributeMaxDynamicSharedMemorySize, 65536);
    cudaFuncSetAttribute(k_s3,  cudaFuncAttributeMaxDynamicSharedMemorySize, 158208);
    cudaFuncSetAttribute(k_qkv, cudaFuncAttributeMaxDynamicSharedMemorySize, SM_QKV);
    cudaFuncSetAttribute(k_attnff, cudaFuncAttributeMaxDynamicSharedMemorySize, SM_ATTNFF);

    k_s1<<<3328, 256>>>(spec, c1w, c1b);
    k_s2<<<dim3(64,8), 256, 65536>>>(c2w, c2b);
    k_s3<<<dim3(32,8), 512, 158208>>>(c3w, c3b);
    for (int L=0; L<11; L++){
        k_qkv<<<256, 512, SM_QKV>>>(Wq+L*4096, bq+L*64, Wk+L*4096, bk+L*64,
                                    Wv+L*4096, bv+L*64, g1+L*64, be1+L*64);
        k_attnff<<<256, 512, SM_ATTNFF>>>(Er+L*384, 1<<L,
                                          W1+L*4096, b1+L*64, W2+L*4096, b2+L*64,
                                          g2+L*64, be2+L*64);
    }
    k_out<<<128, 256>>>(ow, ob, (float*)d_out);
}

// round 12
// speedup vs baseline: 1.0732x; 1.0732x over previous
#include <cuda_runtime.h>
#include <math.h>
#include <stdint.h>

#define TT 4096
#define NB 8
#define NBT (NB*TT)

__device__ __align__(256) float g_s1[NB*208*TT];
__device__ __align__(256) float g_s2[NB*160*TT];
__device__ __align__(256) float g_x [NBT*64];
__device__ __align__(256) float g_q [NBT*64];
__device__ __align__(256) float g_k [NBT*64];
__device__ __align__(256) float g_v [NBT*64];

__device__ __forceinline__ uint32_t f2tf32(float x){
    uint32_t r; asm("cvt.rna.tf32.f32 %0, %1;" : "=r"(r) : "f"(x)); return r;
}

#define MMA_TF32(d, a0,a1,a2,a3, b0,b1) \
  asm volatile("mma.sync.aligned.m16n8k8.row.col.f32.tf32.tf32.f32 " \
      "{%0,%1,%2,%3}, {%4,%5,%6,%7}, {%8,%9}, {%0,%1,%2,%3};" \
      : "+f"(d[0]), "+f"(d[1]), "+f"(d[2]), "+f"(d[3]) \
      : "r"(a0), "r"(a1), "r"(a2), "r"(a3), "r"(b0), "r"(b1))

// ============ stage 1: causal conv (1x3) + maxpool3(freq) + relu ============
__global__ void k_s1(const float* __restrict__ spec, const float* __restrict__ w,
                     const float* __restrict__ bias){
    int id = blockIdx.x*256 + threadIdx.x;
    int t  = id & (TT-1);
    int r  = id >> 12;
    int f2 = r % 26, b = r / 26;
    const float* sp = spec + (size_t)(b*81 + f2*3)*TT + t;
    float s[5][3];
    #pragma unroll
    for (int j=0;j<5;j++)
        #pragma unroll
        for (int i=0;i<3;i++)
            s[j][i] = (t+i < TT) ? sp[j*TT+i] : 0.f;
    #pragma unroll
    for (int c=0;c<8;c++){
        float a0=0.f,a1=0.f,a2=0.f;
        #pragma unroll
        for (int i=0;i<3;i++){
            if (t+i < TT){
                float w0=__ldg(w+(i*8+c)*3+0), w1=__ldg(w+(i*8+c)*3+1), w2=__ldg(w+(i*8+c)*3+2);
                float bb=__ldg(bias+i*8+c);
                a0 += bb + w0*s[0][i]+w1*s[1][i]+w2*s[2][i];
                a1 += bb + w0*s[1][i]+w1*s[2][i]+w2*s[3][i];
                a2 += bb + w0*s[2][i]+w1*s[3][i]+w2*s[4][i];
            }
        }
        float m = fmaxf(fmaxf(a0,a1),a2);
        g_s1[((size_t)(b*8+c)*26+f2)*TT + t] = fmaxf(m, 0.f);
    }
}

// ============ stage 2: conv (1x12) + maxpool3 + relu ============
__global__ void k_s2(const float* __restrict__ w2, const float* __restrict__ b2){
    extern __shared__ float sm[];
    float* s1s = sm;            // [208][64]
    float* ws  = sm + 208*64;   // 3072
    int tid = threadIdx.x, b = blockIdx.y, t0 = blockIdx.x*64;
    for (int i=tid; i<208*64; i+=256){
        int tl = i & 63, fr = i >> 6;
        s1s[i] = g_s1[((size_t)(b*208+fr))*TT + t0 + tl];
    }
    for (int i=tid; i<3072; i+=256) ws[i] = w2[i];
    __syncthreads();
    int tl = tid & 63, g = tid >> 6;
    for (int cb=0; cb<2; cb++){
        int co0 = g*8 + cb*4;
        float acc[4][5][3];
        #pragma unroll
        for (int u=0;u<4;u++){
            float bb = __ldg(b2 + co0 + u);
            #pragma unroll
            for (int f2=0;f2<5;f2++){ acc[u][f2][0]=bb; acc[u][f2][1]=bb; acc[u][f2][2]=bb; }
        }
        for (int cin=0; cin<8; cin++){
            float sv[26];
            #pragma unroll
            for (int ff=0; ff<26; ff++) sv[ff] = s1s[(cin*26+ff)*64 + tl];
            float w[4][12];
            #pragma unroll
            for (int u=0;u<4;u++)
                #pragma unroll
                for (int k=0;k<12;k++) w[u][k] = ws[(co0+u)*96 + cin*12 + k];
            #pragma unroll
            for (int f2=0; f2<5; f2++)
                #pragma unroll
                for (int k=0;k<12;k++)
                    #pragma unroll
                    for (int u=0;u<4;u++){
                        float wk = w[u][k];
                        acc[u][f2][0] += wk*sv[f2*3+k+0];
                        acc[u][f2][1] += wk*sv[f2*3+k+1];
                        acc[u][f2][2] += wk*sv[f2*3+k+2];
                    }
        }
        #pragma unroll
        for (int u=0;u<4;u++)
            #pragma unroll
            for (int f2=0;f2<5;f2++){
                float m = fmaxf(fmaxf(acc[u][f2][0],acc[u][f2][1]),acc[u][f2][2]);
                g_s2[((size_t)((b*32+co0+u)*5+f2))*TT + t0 + tl] = fmaxf(m, 0.f);
            }
    }
}

// ============ stage 3: causal conv (1x3, cin32,co64) + maxpool3 + relu ============
__global__ void __launch_bounds__(512) k_s3(const float* __restrict__ w3, const float* __restrict__ b3){
    extern __shared__ float sm[];
    float* s2s = sm;              // [160][132]
    float* w3s = sm + 160*132;    // 18432
    int tid = threadIdx.x, b = blockIdx.y, t0 = blockIdx.x*128;
    for (int i=tid; i<160*132; i+=512){
        int tl = i % 132, fr = i / 132;
        int tg = t0 + tl;
        s2s[i] = (tg < TT && tl < 130) ? g_s2[((size_t)(b*160+fr))*TT + tg] : 0.f;
    }
    for (int i=tid; i<18432; i+=512){
        int co = i & 63, r = i >> 6;
        int k = r % 3; r /= 3;
        int cin = r & 31, ii = r >> 5;
        w3s[i] = w3[((size_t)(ii*64+co)*32+cin)*3 + k];
    }
    __syncthreads();
    int co = tid & 63, tg8 = tid >> 6;
    float bb0 = __ldg(b3+co), bb1 = __ldg(b3+64+co), bb2 = __ldg(b3+128+co);
    for (int chunk=0; chunk<2; chunk++){
        int tlbase = tg8*16 + chunk*8;
        float acc[8][3];
        #pragma unroll
        for (int rr=0;rr<8;rr++){ acc[rr][0]=0.f; acc[rr][1]=0.f; acc[rr][2]=0.f; }
        for (int cin=0; cin<32; cin++){
            float sv[5][12];
            #pragma unroll
            for (int ff=0; ff<5; ff++){
                const float4* p = (const float4*)(s2s + (cin*5+ff)*132 + tlbase);
                float4 u0=p[0], u1=p[1], u2=p[2];
                sv[ff][0]=u0.x; sv[ff][1]=u0.y; sv[ff][2]=u0.z; sv[ff][3]=u0.w;
                sv[ff][4]=u1.x; sv[ff][5]=u1.y; sv[ff][6]=u1.z; sv[ff][7]=u1.w;
                sv[ff][8]=u2.x; sv[ff][9]=u2.y; sv[ff][10]=u2.z; sv[ff][11]=u2.w;
            }
            #pragma unroll
            for (int ii=0; ii<3; ii++)
                #pragma unroll
                for (int k=0; k<3; k++){
                    float wk = w3s[((ii*32+cin)*3+k)*64 + co];
                    #pragma unroll
                    for (int f=0; f<3; f++)
                        #pragma unroll
                        for (int rr=0; rr<8; rr++)
                            acc[rr][f] += wk*sv[f+k][rr+ii];
                }
        }
        #pragma unroll
        for (int rr=0; rr<8; rr++){
            int tg = t0 + tlbase + rr;
            float a0=acc[rr][0]+bb0, a1=acc[rr][1]+bb0, a2=acc[rr][2]+bb0;
            if (tg+1 < TT){ a0+=bb1; a1+=bb1; a2+=bb1; }
            if (tg+2 < TT){ a0+=bb2; a1+=bb2; a2+=bb2; }
            float m = fmaxf(fmaxf(a0,a1),a2);
            g_x[((size_t)(b*TT+tg))*64 + co] = fmaxf(m, 0.f);
        }
    }
}

// ============ LN1 + QKV via 3xTF32 mma (128 tok/block, 1024 thr = 32 warps) ============
// SMEM: Wh[64][200] Wl[64][200], Hh[128][68], Hl[128][68], bs[192]
__global__ void __launch_bounds__(1024) k_qkv(
        const float* __restrict__ Wq, const float* __restrict__ bq,
        const float* __restrict__ Wk, const float* __restrict__ bk,
        const float* __restrict__ Wv, const float* __restrict__ bv,
        const float* __restrict__ gam, const float* __restrict__ bet){
    extern __shared__ char smraw[];
    uint32_t* Wh = (uint32_t*)smraw;          // 12800
    uint32_t* Wl = Wh + 12800;                // 12800
    uint32_t* Hh = Wl + 12800;                // 8704
    uint32_t* Hl = Hh + 8704;                 // 8704
    float*    bs = (float*)(Hl + 8704);       // 192
    int tid = threadIdx.x;

    for (int i=tid; i<4096; i+=1024){
        int col = i >> 6, d = i & 63;
        float wq = Wq[i], wk = Wk[i], wv = Wv[i];
        uint32_t h;
        h = f2tf32(wq); Wh[d*200+col]     = h; Wl[d*200+col]     = f2tf32(wq - __uint_as_float(h));
        h = f2tf32(wk); Wh[d*200+64+col]  = h; Wl[d*200+64+col]  = f2tf32(wk - __uint_as_float(h));
        h = f2tf32(wv); Wh[d*200+128+col] = h; Wl[d*200+128+col] = f2tf32(wv - __uint_as_float(h));
    }
    if (tid < 64){ bs[tid]=bq[tid]; bs[64+tid]=bk[tid]; bs[128+tid]=bv[tid]; }

    // LN1: 8 threads per token, 8 dims each
    {
        int tok = tid >> 3, lane8 = tid & 7;
        int gtok = blockIdx.x*128 + tok;
        const float* xr = g_x + (size_t)gtok*64 + lane8*8;
        float4 u0 = *(const float4*)xr, u1 = *(const float4*)(xr+4);
        float v[8] = {u0.x,u0.y,u0.z,u0.w,u1.x,u1.y,u1.z,u1.w};
        float s=0.f, ss=0.f;
        #pragma unroll
        for (int m=0;m<8;m++){ s += v[m]; ss += v[m]*v[m]; }
        s += __shfl_xor_sync(0xffffffffu,s,1); ss += __shfl_xor_sync(0xffffffffu,ss,1);
        s += __shfl_xor_sync(0xffffffffu,s,2); ss += __shfl_xor_sync(0xffffffffu,ss,2);
        s += __shfl_xor_sync(0xffffffffu,s,4); ss += __shfl_xor_sync(0xffffffffu,ss,4);
        float mean = s*(1.f/64.f);
        float var  = ss*(1.f/64.f) - mean*mean;
        float rstd = rsqrtf(fmaxf(var,0.f) + 1e-5f);
        #pragma unroll
        for (int m=0;m<8;m++){
            int dd = lane8*8+m;
            float hv = (v[m]-mean)*rstd*__ldg(gam+dd) + __ldg(bet+dd);
            uint32_t hb = f2tf32(hv);
            Hh[tok*68+dd] = hb;
            Hl[tok*68+dd] = f2tf32(hv - __uint_as_float(hb));
        }
    }
    __syncthreads();

    // 32 warps = 8 m-groups (16 rows) x 4 n-groups (48 cols)
    int lane = tid & 31, w = tid >> 5;
    int m0 = (w >> 2) << 4;
    int n0 = (w & 3) * 48;
    float acc[6][4];
    #pragma unroll
    for (int nt=0;nt<6;nt++){ acc[nt][0]=0.f; acc[nt][1]=0.f; acc[nt][2]=0.f; acc[nt][3]=0.f; }
    int arow = m0 + (lane>>2);
    #pragma unroll
    for (int kt=0; kt<8; kt++){
        int k0 = kt*8;
        int ai = arow*68 + k0 + (lane&3);
        uint32_t ah0=Hh[ai], ah1=Hh[ai+544], ah2=Hh[ai+4], ah3=Hh[ai+548];
        uint32_t al0=Hl[ai], al1=Hl[ai+544], al2=Hl[ai+4], al3=Hl[ai+548];
        int bi = (k0 + (lane&3))*200 + n0 + (lane>>2);
        #pragma unroll
        for (int nt=0; nt<6; nt++){
            uint32_t bh0=Wh[bi+nt*8], bh1=Wh[bi+nt*8+800];
            uint32_t bl0=Wl[bi+nt*8], bl1=Wl[bi+nt*8+800];
            MMA_TF32(acc[nt], al0,al1,al2,al3, bh0,bh1);
            MMA_TF32(acc[nt], ah0,ah1,ah2,ah3, bl0,bl1);
            MMA_TF32(acc[nt], ah0,ah1,ah2,ah3, bh0,bh1);
        }
    }
    int gt = blockIdx.x*128 + m0 + (lane>>2);
    #pragma unroll
    for (int nt=0; nt<6; nt++){
        int colg = n0 + nt*8 + 2*(lane&3);
        int seg = colg >> 6, cl = colg & 63;
        float* dst = (seg==0) ? g_q : (seg==1) ? g_k : g_v;
        float b0 = bs[colg], b1 = bs[colg+1];
        float2 v0; v0.x = acc[nt][0] + b0; v0.y = acc[nt][1] + b1;
        *(float2*)(dst + (size_t)gt*64 + cl) = v0;
        float2 v1; v1.x = acc[nt][2] + b0; v1.y = acc[nt][3] + b1;
        *(float2*)(dst + (size_t)(gt+8)*64 + cl) = v1;
    }
}

// ============ attention + residual + LN2 + FF + residual (fused, 512 thr) ============
__global__ void __launch_bounds__(512, 2) k_attnff(
        const float* __restrict__ Er, int shift,
        const float* __restrict__ W1p, const float* __restrict__ b1p,
        const float* __restrict__ W2p, const float* __restrict__ b2p,
        const float* __restrict__ gam, const float* __restrict__ bet){
    extern __shared__ float sm[];
    float* W1s = sm;            // [64][66]
    float* W2s = sm + 4224;     // [64][66]
    float* bs  = sm + 8448;     // 128
    float* xs  = sm + 8576;     // [64][68]
    float* hs  = sm + 12928;    // [64][68]
    int tid = threadIdx.x;
    for (int i=tid; i<4096; i+=512){
        int col = i >> 6, d = i & 63;
        W1s[d*66+col] = W1p[i];
        W2s[d*66+col] = W2p[i];
    }
    if (tid < 64){ bs[tid]=b1p[tid]; bs[64+tid]=b2p[tid]; }

    // ---- attention: 8 threads/token, 1 head each ----
    {
        int tok = tid >> 3, h = tid & 7;
        int gtok = blockIdx.x*64 + tok;
        int b = gtok >> 12, t = gtok & (TT-1);
        size_t bt = (size_t)b*TT + t;
        int sh[6]; sh[0]=0; sh[1]=0; sh[2]=shift; sh[3]=2*shift; sh[4]=3*shift; sh[5]=4*shift;
        const float* qp = g_q + bt*64 + h*8;
        float4 q0 = *(const float4*)qp, q1 = *(const float4*)(qp+4);
        float q[8] = {q0.x,q0.y,q0.z,q0.w,q1.x,q1.y,q1.z,q1.w};
        const float* er = Er + h*48;
        float lg[6];
        #pragma unroll
        for (int j=0;j<6;j++){
            float qe = 0.f;
            #pragma unroll
            for (int d=0;d<8;d++) qe += q[d]*__ldg(er + d*6 + j);
            lg[j] = qe;
        }
        #pragma unroll
        for (int j=0;j<6;j++){
            int tp = t - sh[j];
            float qk = 0.f;
            if (tp >= 0){
                const float* kp = g_k + ((size_t)b*TT+tp)*64 + h*8;
                float4 k0 = *(const float4*)kp, k1 = *(const float4*)(kp+4);
                qk = q[0]*k0.x + q[1]*k0.y + q[2]*k0.z + q[3]*k0.w
                   + q[4]*k1.x + q[5]*k1.y + q[6]*k1.z + q[7]*k1.w;
            }
            lg[j] = (qk + lg[j]) * 0.3535533905932738f;
        }
        float mx = lg[0];
        #pragma unroll
        for (int j=1;j<6;j++) mx = fmaxf(mx, lg[j]);
        float e[6], se = 0.f;
        #pragma unroll
        for (int j=0;j<6;j++){ e[j] = expf(lg[j]-mx); se += e[j]; }
        float inv = 1.f/se;
        float o[8] = {0,0,0,0,0,0,0,0};
        #pragma unroll
        for (int j=0;j<6;j++){
            int tp = t - sh[j];
            if (tp >= 0){
                const float* vp = g_v + ((size_t)b*TT+tp)*64 + h*8;
                float4 v0 = *(const float4*)vp, v1 = *(const float4*)(vp+4);
                float a = e[j];
                o[0]+=a*v0.x; o[1]+=a*v0.y; o[2]+=a*v0.z; o[3]+=a*v0.w;
                o[4]+=a*v1.x; o[5]+=a*v1.y; o[6]+=a*v1.z; o[7]+=a*v1.w;
            }
        }
        const float* xp = g_x + (size_t)gtok*64 + h*8;
        float4 x0 = *(const float4*)xp, x1 = *(const float4*)(xp+4);
        float* xd = xs + tok*68 + h*8;
        xd[0]=x0.x+o[0]*inv; xd[1]=x0.y+o[1]*inv; xd[2]=x0.z+o[2]*inv; xd[3]=x0.w+o[3]*inv;
        xd[4]=x1.x+o[4]*inv; xd[5]=x1.y+o[5]*inv; xd[6]=x1.z+o[6]*inv; xd[7]=x1.w+o[7]*inv;
    }
    __syncthreads();

    // ---- LN2: 8 threads/token ----
    {
        int tok = tid >> 3, lane = tid & 7;
        float v[8];
        #pragma unroll
        for (int m=0;m<8;m++) v[m] = xs[tok*68 + lane*8 + m];
        float s=0.f, ss=0.f;
        #pragma unroll
        for (int m=0;m<8;m++){ s += v[m]; ss += v[m]*v[m]; }
        s += __shfl_xor_sync(0xffffffffu,s,1); ss += __shfl_xor_sync(0xffffffffu,ss,1);
        s += __shfl_xor_sync(0xffffffffu,s,2); ss += __shfl_xor_sync(0xffffffffu,ss,2);
        s += __shfl_xor_sync(0xffffffffu,s,4); ss += __shfl_xor_sync(0xffffffffu,ss,4);
        float mean = s*(1.f/64.f);
        float var  = ss*(1.f/64.f) - mean*mean;
        float rstd = rsqrtf(fmaxf(var,0.f) + 1e-5f);
        #pragma unroll
        for (int m=0;m<8;m++){
            int dd = lane*8+m;
            hs[tok*68+dd] = (v[m]-mean)*rstd*__ldg(gam+dd) + __ldg(bet+dd);
        }
    }
    __syncthreads();

    // ---- GEMM1: 32 lanes x 16 rowgroups, 4 tokens x 2 adj cols ----
    int c2 = tid & 31, rg = tid >> 5;
    float acc[4][2];
    #pragma unroll
    for (int r=0;r<4;r++){ acc[r][0]=0.f; acc[r][1]=0.f; }
    #pragma unroll 4
    for (int d=0; d<64; d+=4){
        float hv[4][4];
        #pragma unroll
        for (int r=0;r<4;r++){
            float4 u = *(const float4*)(hs + (rg*4+r)*68 + d);
            hv[r][0]=u.x; hv[r][1]=u.y; hv[r][2]=u.z; hv[r][3]=u.w;
        }
        #pragma unroll
        for (int dd=0; dd<4; dd++){
            float2 w01 = *(const float2*)(W1s + (d+dd)*66 + 2*c2);
            #pragma unroll
            for (int r=0;r<4;r++){
                acc[r][0] += hv[r][dd]*w01.x;
                acc[r][1] += hv[r][dd]*w01.y;
            }
        }
    }
    __syncthreads();
    #pragma unroll
    for (int r=0;r<4;r++)
        #pragma unroll
        for (int e=0;e<2;e++){
            float z = acc[r][e] + bs[2*c2 + e];
            hs[(rg*4+r)*68 + 2*c2 + e] = 0.5f*z*(1.f + erff(z*0.7071067811865475f));
        }
    __syncthreads();

    // ---- GEMM2 + residual ----
    float acc2[4][2];
    #pragma unroll
    for (int r=0;r<4;r++){ acc2[r][0]=0.f; acc2[r][1]=0.f; }
    #pragma unroll 4
    for (int d=0; d<64; d+=4){
        float hv[4][4];
        #pragma unroll
        for (int r=0;r<4;r++){
            float4 u = *(const float4*)(hs + (rg*4+r)*68 + d);
            hv[r][0]=u.x; hv[r][1]=u.y; hv[r][2]=u.z; hv[r][3]=u.w;
        }
        #pragma unroll
        for (int dd=0; dd<4; dd++){
            float2 w01 = *(const float2*)(W2s + (d+dd)*66 + 2*c2);
            #pragma unroll
            for (int r=0;r<4;r++){
                acc2[r][0] += hv[r][dd]*w01.x;
                acc2[r][1] += hv[r][dd]*w01.y;
            }
        }
    }
    int gt0 = blockIdx.x*64 + rg*4;
    #pragma unroll
    for (int r=0;r<4;r++){
        float2 val;
        val.x = xs[(rg*4+r)*68 + 2*c2]     + acc2[r][0] + bs[64 + 2*c2];
        val.y = xs[(rg*4+r)*68 + 2*c2 + 1] + acc2[r][1] + bs[64 + 2*c2 + 1];
        *(float2*)(g_x + ((size_t)(gt0+r))*64 + 2*c2) = val;
    }
}

// ============ 1x1 conv out + sigmoid ============
__global__ void k_out(const float* __restrict__ ow, const float* __restrict__ ob,
                      float* __restrict__ out){
    int id = blockIdx.x*256 + threadIdx.x;
    int t = id & (TT-1), b = id >> 12;
    const float4* xp = (const float4*)(g_x + (size_t)id*64);
    float a0 = __ldg(ob), a1 = __ldg(ob+1);
    #pragma unroll
    for (int d4=0; d4<16; d4++){
        float4 xv = xp[d4];
        a0 += xv.x*__ldg(ow+d4*4) + xv.y*__ldg(ow+d4*4+1) + xv.z*__ldg(ow+d4*4+2) + xv.w*__ldg(ow+d4*4+3);
        a1 += xv.x*__ldg(ow+64+d4*4) + xv.y*__ldg(ow+64+d4*4+1) + xv.z*__ldg(ow+64+d4*4+2) + xv.w*__ldg(ow+64+d4*4+3);
    }
    out[((size_t)(b*2))*TT + t]   = 1.f/(1.f+expf(-a0));
    out[((size_t)(b*2+1))*TT + t] = 1.f/(1.f+expf(-a1));
}

extern "C" void kernel_launch(void* const* d_in, const int* in_sizes, int n_in,
                              void* d_out, int out_size){
    const float* spec = (const float*)d_in[0];
    const float* c1w = (const float*)d_in[1];
    const float* c1b = (const float*)d_in[2];
    const float* c2w = (const float*)d_in[3];
    const float* c2b = (const float*)d_in[4];
    const float* c3w = (const float*)d_in[5];
    const float* c3b = (const float*)d_in[6];
    const float* Wq  = (const float*)d_in[7];
    const float* bq  = (const float*)d_in[8];
    const float* Wk  = (const float*)d_in[9];
    const float* bk  = (const float*)d_in[10];
    const float* Wv  = (const float*)d_in[11];
    const float* bv  = (const float*)d_in[12];
    const float* Er  = (const float*)d_in[13];
    const float* g1  = (const float*)d_in[14];
    const float* be1 = (const float*)d_in[15];
    const float* W1  = (const float*)d_in[16];
    const float* b1  = (const float*)d_in[17];
    const float* W2  = (const float*)d_in[18];
    const float* b2  = (const float*)d_in[19];
    const float* g2  = (const float*)d_in[20];
    const float* be2 = (const float*)d_in[21];
    const float* ow  = (const float*)d_in[22];
    const float* ob  = (const float*)d_in[23];

    cudaFuncSetAttribute(k_s2,  cudaFuncAttributeMaxDynamicSharedMemorySize, 65536);
    cudaFuncSetAttribute(k_s3,  cudaFuncAttributeMaxDynamicSharedMemorySize, 158208);
    cudaFuncSetAttribute(k_qkv, cudaFuncAttributeMaxDynamicSharedMemorySize, 172800);
    cudaFuncSetAttribute(k_attnff, cudaFuncAttributeMaxDynamicSharedMemorySize, 69120);

    k_s1<<<3328, 256>>>(spec, c1w, c1b);
    k_s2<<<dim3(64,8), 256, 65536>>>(c2w, c2b);
    k_s3<<<dim3(32,8), 512, 158208>>>(c3w, c3b);
    for (int L=0; L<11; L++){
        k_qkv<<<256, 1024, 172800>>>(Wq+L*4096, bq+L*64, Wk+L*4096, bk+L*64,
                                     Wv+L*4096, bv+L*64, g1+L*64, be1+L*64);
        k_attnff<<<512, 512, 69120>>>(Er+L*384, 1<<L,
                                      W1+L*4096, b1+L*64, W2+L*4096, b2+L*64,
                                      g2+L*64, be2+L*64);
    }
    k_out<<<128, 256>>>(ow, ob, (float*)d_out);
}

// round 13
// speedup vs baseline: 1.3619x; 1.2690x over previous
#include <cuda_runtime.h>
#include <cuda_bf16.h>
#include <math.h>
#include <stdint.h>

#define TT 4096
#define NB 8
#define NBT (NB*TT)

__device__ __align__(256) float g_s1[NB*208*TT];
__device__ __align__(256) float g_s2[NB*160*TT];
__device__ __align__(256) float g_x [NBT*64];
__device__ __align__(256) float g_q [NBT*64];
__device__ __align__(256) float g_k [NBT*64];
__device__ __align__(256) float g_v [NBT*64];

__device__ __forceinline__ uint32_t pk_hi(float a, float b){
    __nv_bfloat162 t; t.x = __float2bfloat16_rn(a); t.y = __float2bfloat16_rn(b);
    return *(uint32_t*)&t;
}
__device__ __forceinline__ uint32_t pk_lo(float a, float b){
    __nv_bfloat162 t;
    t.x = __float2bfloat16_rn(a - __bfloat162float(__float2bfloat16_rn(a)));
    t.y = __float2bfloat16_rn(b - __bfloat162float(__float2bfloat16_rn(b)));
    return *(uint32_t*)&t;
}

#define MMA_BF16(d, a0,a1,a2,a3, b0,b1) \
  asm volatile("mma.sync.aligned.m16n8k16.row.col.f32.bf16.bf16.f32 " \
      "{%0,%1,%2,%3}, {%4,%5,%6,%7}, {%8,%9}, {%0,%1,%2,%3};" \
      : "+f"(d[0]), "+f"(d[1]), "+f"(d[2]), "+f"(d[3]) \
      : "r"(a0), "r"(a1), "r"(a2), "r"(a3), "r"(b0), "r"(b1))

// ============ stage 1: causal conv (1x3) + maxpool3(freq) + relu ============
__global__ void k_s1(const float* __restrict__ spec, const float* __restrict__ w,
                     const float* __restrict__ bias){
    int id = blockIdx.x*256 + threadIdx.x;
    int t  = id & (TT-1);
    int r  = id >> 12;
    int f2 = r % 26, b = r / 26;
    const float* sp = spec + (size_t)(b*81 + f2*3)*TT + t;
    float s[5][3];
    #pragma unroll
    for (int j=0;j<5;j++)
        #pragma unroll
        for (int i=0;i<3;i++)
            s[j][i] = (t+i < TT) ? sp[j*TT+i] : 0.f;
    #pragma unroll
    for (int c=0;c<8;c++){
        float a0=0.f,a1=0.f,a2=0.f;
        #pragma unroll
        for (int i=0;i<3;i++){
            if (t+i < TT){
                float w0=__ldg(w+(i*8+c)*3+0), w1=__ldg(w+(i*8+c)*3+1), w2=__ldg(w+(i*8+c)*3+2);
                float bb=__ldg(bias+i*8+c);
                a0 += bb + w0*s[0][i]+w1*s[1][i]+w2*s[2][i];
                a1 += bb + w0*s[1][i]+w1*s[2][i]+w2*s[3][i];
                a2 += bb + w0*s[2][i]+w1*s[3][i]+w2*s[4][i];
            }
        }
        float m = fmaxf(fmaxf(a0,a1),a2);
        g_s1[((size_t)(b*8+c)*26+f2)*TT + t] = fmaxf(m, 0.f);
    }
}

// ============ stage 2: conv (1x12) + maxpool3 + relu ============
__global__ void k_s2(const float* __restrict__ w2, const float* __restrict__ b2){
    extern __shared__ float sm[];
    float* s1s = sm;            // [208][64]
    float* ws  = sm + 208*64;   // 3072
    int tid = threadIdx.x, b = blockIdx.y, t0 = blockIdx.x*64;
    for (int i=tid; i<208*64; i+=256){
        int tl = i & 63, fr = i >> 6;
        s1s[i] = g_s1[((size_t)(b*208+fr))*TT + t0 + tl];
    }
    for (int i=tid; i<3072; i+=256) ws[i] = w2[i];
    __syncthreads();
    int tl = tid & 63, g = tid >> 6;
    for (int cb=0; cb<2; cb++){
        int co0 = g*8 + cb*4;
        float acc[4][5][3];
        #pragma unroll
        for (int u=0;u<4;u++){
            float bb = __ldg(b2 + co0 + u);
            #pragma unroll
            for (int f2=0;f2<5;f2++){ acc[u][f2][0]=bb; acc[u][f2][1]=bb; acc[u][f2][2]=bb; }
        }
        for (int cin=0; cin<8; cin++){
            float sv[26];
            #pragma unroll
            for (int ff=0; ff<26; ff++) sv[ff] = s1s[(cin*26+ff)*64 + tl];
            float w[4][12];
            #pragma unroll
            for (int u=0;u<4;u++)
                #pragma unroll
                for (int k=0;k<12;k++) w[u][k] = ws[(co0+u)*96 + cin*12 + k];
            #pragma unroll
            for (int f2=0; f2<5; f2++)
                #pragma unroll
                for (int k=0;k<12;k++)
                    #pragma unroll
                    for (int u=0;u<4;u++){
                        float wk = w[u][k];
                        acc[u][f2][0] += wk*sv[f2*3+k+0];
                        acc[u][f2][1] += wk*sv[f2*3+k+1];
                        acc[u][f2][2] += wk*sv[f2*3+k+2];
                    }
        }
        #pragma unroll
        for (int u=0;u<4;u++)
            #pragma unroll
            for (int f2=0;f2<5;f2++){
                float m = fmaxf(fmaxf(acc[u][f2][0],acc[u][f2][1]),acc[u][f2][2]);
                g_s2[((size_t)((b*32+co0+u)*5+f2))*TT + t0 + tl] = fmaxf(m, 0.f);
            }
    }
}

// ============ stage 3: causal conv (1x3, cin32,co64) + maxpool3 + relu ============
__global__ void __launch_bounds__(512) k_s3(const float* __restrict__ w3, const float* __restrict__ b3){
    extern __shared__ float sm[];
    float* s2s = sm;              // [160][132]
    float* w3s = sm + 160*132;    // 18432
    int tid = threadIdx.x, b = blockIdx.y, t0 = blockIdx.x*128;
    for (int i=tid; i<160*132; i+=512){
        int tl = i % 132, fr = i / 132;
        int tg = t0 + tl;
        s2s[i] = (tg < TT && tl < 130) ? g_s2[((size_t)(b*160+fr))*TT + tg] : 0.f;
    }
    for (int i=tid; i<18432; i+=512){
        int co = i & 63, r = i >> 6;
        int k = r % 3; r /= 3;
        int cin = r & 31, ii = r >> 5;
        w3s[i] = w3[((size_t)(ii*64+co)*32+cin)*3 + k];
    }
    __syncthreads();
    int co = tid & 63, tg8 = tid >> 6;
    float bb0 = __ldg(b3+co), bb1 = __ldg(b3+64+co), bb2 = __ldg(b3+128+co);
    for (int chunk=0; chunk<2; chunk++){
        int tlbase = tg8*16 + chunk*8;
        float acc[8][3];
        #pragma unroll
        for (int rr=0;rr<8;rr++){ acc[rr][0]=0.f; acc[rr][1]=0.f; acc[rr][2]=0.f; }
        for (int cin=0; cin<32; cin++){
            float sv[5][12];
            #pragma unroll
            for (int ff=0; ff<5; ff++){
                const float4* p = (const float4*)(s2s + (cin*5+ff)*132 + tlbase);
                float4 u0=p[0], u1=p[1], u2=p[2];
                sv[ff][0]=u0.x; sv[ff][1]=u0.y; sv[ff][2]=u0.z; sv[ff][3]=u0.w;
                sv[ff][4]=u1.x; sv[ff][5]=u1.y; sv[ff][6]=u1.z; sv[ff][7]=u1.w;
                sv[ff][8]=u2.x; sv[ff][9]=u2.y; sv[ff][10]=u2.z; sv[ff][11]=u2.w;
            }
            #pragma unroll
            for (int ii=0; ii<3; ii++)
                #pragma unroll
                for (int k=0; k<3; k++){
                    float wk = w3s[((ii*32+cin)*3+k)*64 + co];
                    #pragma unroll
                    for (int f=0; f<3; f++)
                        #pragma unroll
                        for (int rr=0; rr<8; rr++)
                            acc[rr][f] += wk*sv[f+k][rr+ii];
                }
        }
        #pragma unroll
        for (int rr=0; rr<8; rr++){
            int tg = t0 + tlbase + rr;
            float a0=acc[rr][0]+bb0, a1=acc[rr][1]+bb0, a2=acc[rr][2]+bb0;
            if (tg+1 < TT){ a0+=bb1; a1+=bb1; a2+=bb1; }
            if (tg+2 < TT){ a0+=bb2; a1+=bb2; a2+=bb2; }
            float m = fmaxf(fmaxf(a0,a1),a2);
            g_x[((size_t)(b*TT+tg))*64 + co] = fmaxf(m, 0.f);
        }
    }
}

// ============ LN1 + QKV via 3xBF16 mma (128 tok/block, 1024 thr) ============
// SMEM (uint32): Wh[32][200], Wl[32][200] (bf16x2 kpairs of [Wq|Wk|Wv]),
//                Hh[128][36], Hl[128][36], bs float[192]
__global__ void __launch_bounds__(1024) k_qkv(
        const float* __restrict__ Wq, const float* __restrict__ bq,
        const float* __restrict__ Wk, const float* __restrict__ bk,
        const float* __restrict__ Wv, const float* __restrict__ bv,
        const float* __restrict__ gam, const float* __restrict__ bet){
    extern __shared__ char smraw[];
    uint32_t* Wh = (uint32_t*)smraw;       // 6400
    uint32_t* Wl = Wh + 6400;              // 6400
    uint32_t* Hh = Wl + 6400;              // 4608
    uint32_t* Hl = Hh + 4608;              // 4608
    float*    bs = (float*)(Hl + 4608);    // 192
    int tid = threadIdx.x;

    // stage weights: kp = k-pair (d dims 2kp,2kp+1), c = global out col (0..191)
    for (int i=tid; i<6144; i+=1024){
        int kp = i & 31, c = i >> 5;
        int seg = c >> 6, cl = c & 63;
        const float* Wsrc = (seg==0) ? Wq : (seg==1) ? Wk : Wv;
        float w0 = Wsrc[cl*64 + 2*kp], w1 = Wsrc[cl*64 + 2*kp + 1];
        Wh[kp*200 + c] = pk_hi(w0, w1);
        Wl[kp*200 + c] = pk_lo(w0, w1);
    }
    if (tid < 64){ bs[tid]=bq[tid]; bs[64+tid]=bk[tid]; bs[128+tid]=bv[tid]; }

    // LN1: 8 threads/token, 8 dims each -> 4 kpairs
    {
        int tok = tid >> 3, lane8 = tid & 7;
        int gtok = blockIdx.x*128 + tok;
        const float* xr = g_x + (size_t)gtok*64 + lane8*8;
        float4 u0 = *(const float4*)xr, u1 = *(const float4*)(xr+4);
        float v[8] = {u0.x,u0.y,u0.z,u0.w,u1.x,u1.y,u1.z,u1.w};
        float s=0.f, ss=0.f;
        #pragma unroll
        for (int m=0;m<8;m++){ s += v[m]; ss += v[m]*v[m]; }
        s += __shfl_xor_sync(0xffffffffu,s,1); ss += __shfl_xor_sync(0xffffffffu,ss,1);
        s += __shfl_xor_sync(0xffffffffu,s,2); ss += __shfl_xor_sync(0xffffffffu,ss,2);
        s += __shfl_xor_sync(0xffffffffu,s,4); ss += __shfl_xor_sync(0xffffffffu,ss,4);
        float mean = s*(1.f/64.f);
        float var  = ss*(1.f/64.f) - mean*mean;
        float rstd = rsqrtf(fmaxf(var,0.f) + 1e-5f);
        float h[8];
        #pragma unroll
        for (int m=0;m<8;m++){
            int dd = lane8*8+m;
            h[m] = (v[m]-mean)*rstd*__ldg(gam+dd) + __ldg(bet+dd);
        }
        #pragma unroll
        for (int j=0;j<4;j++){
            Hh[tok*36 + lane8*4 + j] = pk_hi(h[2*j], h[2*j+1]);
            Hl[tok*36 + lane8*4 + j] = pk_lo(h[2*j], h[2*j+1]);
        }
    }
    __syncthreads();

    // 32 warps = 8 m-groups (16 rows) x 4 n-groups (48 cols); K=64 = 4 kt of 16
    int lane = tid & 31, w = tid >> 5;
    int m0 = (w >> 2) << 4;
    int n0 = (w & 3) * 48;
    float acc[6][4];
    #pragma unroll
    for (int nt=0;nt<6;nt++){ acc[nt][0]=0.f; acc[nt][1]=0.f; acc[nt][2]=0.f; acc[nt][3]=0.f; }
    int row = m0 + (lane>>2);
    #pragma unroll
    for (int kt=0; kt<4; kt++){
        int ai = row*36 + kt*8 + (lane&3);
        uint32_t ah0=Hh[ai], ah1=Hh[ai+288], ah2=Hh[ai+4], ah3=Hh[ai+292];
        uint32_t al0=Hl[ai], al1=Hl[ai+288], al2=Hl[ai+4], al3=Hl[ai+292];
        int bi = (kt*8 + (lane&3))*200 + n0 + (lane>>2);
        #pragma unroll
        for (int nt=0; nt<6; nt++){
            uint32_t bh0=Wh[bi+nt*8], bh1=Wh[bi+nt*8+800];
            uint32_t bl0=Wl[bi+nt*8], bl1=Wl[bi+nt*8+800];
            MMA_BF16(acc[nt], al0,al1,al2,al3, bh0,bh1);
            MMA_BF16(acc[nt], ah0,ah1,ah2,ah3, bl0,bl1);
            MMA_BF16(acc[nt], ah0,ah1,ah2,ah3, bh0,bh1);
        }
    }
    int gt = blockIdx.x*128 + row;
    #pragma unroll
    for (int nt=0; nt<6; nt++){
        int colg = n0 + nt*8 + 2*(lane&3);
        int seg = colg >> 6, cl = colg & 63;
        float* dst = (seg==0) ? g_q : (seg==1) ? g_k : g_v;
        float b0 = bs[colg], b1 = bs[colg+1];
        float2 v0; v0.x = acc[nt][0] + b0; v0.y = acc[nt][1] + b1;
        *(float2*)(dst + (size_t)gt*64 + cl) = v0;
        float2 v1; v1.x = acc[nt][2] + b0; v1.y = acc[nt][3] + b1;
        *(float2*)(dst + (size_t)(gt+8)*64 + cl) = v1;
    }
}

// ============ attention + residual + LN2 + FF(3xBF16 mma) + residual (64 tok, 512 thr) ============
// SMEM (u32): W1h[32][72] W1l W2h W2l, hsh[64][36] hsl, xs float[64][68], bs[128]
__global__ void __launch_bounds__(512, 2) k_attnff(
        const float* __restrict__ Er, int shift,
        const float* __restrict__ W1g, const float* __restrict__ b1p,
        const float* __restrict__ W2g, const float* __restrict__ b2p,
        const float* __restrict__ gam, const float* __restrict__ bet){
    extern __shared__ char smraw[];
    uint32_t* W1h = (uint32_t*)smraw;       // 2304
    uint32_t* W1l = W1h + 2304;
    uint32_t* W2h = W1l + 2304;
    uint32_t* W2l = W2h + 2304;
    uint32_t* hsh = W2l + 2304;             // 2304 (64*36)
    uint32_t* hsl = hsh + 2304;
    float*    xs  = (float*)(hsl + 2304);   // 4352 (64*68)
    float*    bs  = xs + 4352;              // 128
    int tid = threadIdx.x;

    for (int i=tid; i<2048; i+=512){
        int kp = i & 31, c = i >> 5;
        float w0 = W1g[c*64 + 2*kp], w1 = W1g[c*64 + 2*kp + 1];
        W1h[kp*72 + c] = pk_hi(w0, w1);
        W1l[kp*72 + c] = pk_lo(w0, w1);
        w0 = W2g[c*64 + 2*kp]; w1 = W2g[c*64 + 2*kp + 1];
        W2h[kp*72 + c] = pk_hi(w0, w1);
        W2l[kp*72 + c] = pk_lo(w0, w1);
    }
    if (tid < 64){ bs[tid]=b1p[tid]; bs[64+tid]=b2p[tid]; }

    // ---- attention: 8 threads/token, 1 head each ----
    {
        int tok = tid >> 3, h = tid & 7;
        int gtok = blockIdx.x*64 + tok;
        int b = gtok >> 12, t = gtok & (TT-1);
        size_t bt = (size_t)b*TT + t;
        int sh[6]; sh[0]=0; sh[1]=0; sh[2]=shift; sh[3]=2*shift; sh[4]=3*shift; sh[5]=4*shift;
        const float* qp = g_q + bt*64 + h*8;
        float4 q0 = *(const float4*)qp, q1 = *(const float4*)(qp+4);
        float q[8] = {q0.x,q0.y,q0.z,q0.w,q1.x,q1.y,q1.z,q1.w};
        const float* er = Er + h*48;
        float lg[6];
        #pragma unroll
        for (int j=0;j<6;j++){
            float qe = 0.f;
            #pragma unroll
            for (int d=0;d<8;d++) qe += q[d]*__ldg(er + d*6 + j);
            lg[j] = qe;
        }
        #pragma unroll
        for (int j=0;j<6;j++){
            int tp = t - sh[j];
            float qk = 0.f;
            if (tp >= 0){
                const float* kp = g_k + ((size_t)b*TT+tp)*64 + h*8;
                float4 k0 = *(const float4*)kp, k1 = *(const float4*)(kp+4);
                qk = q[0]*k0.x + q[1]*k0.y + q[2]*k0.z + q[3]*k0.w
                   + q[4]*k1.x + q[5]*k1.y + q[6]*k1.z + q[7]*k1.w;
            }
            lg[j] = (qk + lg[j]) * 0.3535533905932738f;
        }
        float mx = lg[0];
        #pragma unroll
        for (int j=1;j<6;j++) mx = fmaxf(mx, lg[j]);
        float e[6], se = 0.f;
        #pragma unroll
        for (int j=0;j<6;j++){ e[j] = expf(lg[j]-mx); se += e[j]; }
        float inv = 1.f/se;
        float o[8] = {0,0,0,0,0,0,0,0};
        #pragma unroll
        for (int j=0;j<6;j++){
            int tp = t - sh[j];
            if (tp >= 0){
                const float* vp = g_v + ((size_t)b*TT+tp)*64 + h*8;
                float4 v0 = *(const float4*)vp, v1 = *(const float4*)(vp+4);
                float a = e[j];
                o[0]+=a*v0.x; o[1]+=a*v0.y; o[2]+=a*v0.z; o[3]+=a*v0.w;
                o[4]+=a*v1.x; o[5]+=a*v1.y; o[6]+=a*v1.z; o[7]+=a*v1.w;
            }
        }
        const float* xp = g_x + (size_t)gtok*64 + h*8;
        float4 x0 = *(const float4*)xp, x1 = *(const float4*)(xp+4);
        float* xd = xs + tok*68 + h*8;
        xd[0]=x0.x+o[0]*inv; xd[1]=x0.y+o[1]*inv; xd[2]=x0.z+o[2]*inv; xd[3]=x0.w+o[3]*inv;
        xd[4]=x1.x+o[4]*inv; xd[5]=x1.y+o[5]*inv; xd[6]=x1.z+o[6]*inv; xd[7]=x1.w+o[7]*inv;
    }
    __syncthreads();

    // ---- LN2: 8 threads/token, pack bf16 hi/lo ----
    {
        int tok = tid >> 3, lane8 = tid & 7;
        float v[8];
        #pragma unroll
        for (int m=0;m<8;m++) v[m] = xs[tok*68 + lane8*8 + m];
        float s=0.f, ss=0.f;
        #pragma unroll
        for (int m=0;m<8;m++){ s += v[m]; ss += v[m]*v[m]; }
        s += __shfl_xor_sync(0xffffffffu,s,1); ss += __shfl_xor_sync(0xffffffffu,ss,1);
        s += __shfl_xor_sync(0xffffffffu,s,2); ss += __shfl_xor_sync(0xffffffffu,ss,2);
        s += __shfl_xor_sync(0xffffffffu,s,4); ss += __shfl_xor_sync(0xffffffffu,ss,4);
        float mean = s*(1.f/64.f);
        float var  = ss*(1.f/64.f) - mean*mean;
        float rstd = rsqrtf(fmaxf(var,0.f) + 1e-5f);
        float h[8];
        #pragma unroll
        for (int m=0;m<8;m++){
            int dd = lane8*8+m;
            h[m] = (v[m]-mean)*rstd*__ldg(gam+dd) + __ldg(bet+dd);
        }
        #pragma unroll
        for (int j=0;j<4;j++){
            hsh[tok*36 + lane8*4 + j] = pk_hi(h[2*j], h[2*j+1]);
            hsl[tok*36 + lane8*4 + j] = pk_lo(h[2*j], h[2*j+1]);
        }
    }
    __syncthreads();

    // 16 warps = 4 m-groups (16 rows) x 4 n-groups (16 cols)
    int lane = tid & 31, w = tid >> 5;
    int m0 = (w >> 2) << 4;
    int n0 = (w & 3) * 16;
    int row = m0 + (lane>>2);

    // ---- GEMM1 (3xBF16) ----
    float acc[2][4];
    #pragma unroll
    for (int nt=0;nt<2;nt++){ acc[nt][0]=0.f; acc[nt][1]=0.f; acc[nt][2]=0.f; acc[nt][3]=0.f; }
    #pragma unroll
    for (int kt=0; kt<4; kt++){
        int ai = row*36 + kt*8 + (lane&3);
        uint32_t ah0=hsh[ai], ah1=hsh[ai+288], ah2=hsh[ai+4], ah3=hsh[ai+292];
        uint32_t al0=hsl[ai], al1=hsl[ai+288], al2=hsl[ai+4], al3=hsl[ai+292];
        int bi = (kt*8 + (lane&3))*72 + n0 + (lane>>2);
        #pragma unroll
        for (int nt=0; nt<2; nt++){
            uint32_t bh0=W1h[bi+nt*8], bh1=W1h[bi+nt*8+288];
            uint32_t bl0=W1l[bi+nt*8], bl1=W1l[bi+nt*8+288];
            MMA_BF16(acc[nt], al0,al1,al2,al3, bh0,bh1);
            MMA_BF16(acc[nt], ah0,ah1,ah2,ah3, bl0,bl1);
            MMA_BF16(acc[nt], ah0,ah1,ah2,ah3, bh0,bh1);
        }
    }
    __syncthreads();
    // gelu -> repack as A for GEMM2 (col-pair == k-pair)
    #pragma unroll
    for (int nt=0; nt<2; nt++){
        int colg = n0 + nt*8 + 2*(lane&3);
        int kp = (colg >> 1);
        float bb0 = bs[colg], bb1 = bs[colg+1];
        float z0 = acc[nt][0] + bb0; z0 = 0.5f*z0*(1.f + erff(z0*0.7071067811865475f));
        float z1 = acc[nt][1] + bb1; z1 = 0.5f*z1*(1.f + erff(z1*0.7071067811865475f));
        hsh[row*36 + kp] = pk_hi(z0, z1);
        hsl[row*36 + kp] = pk_lo(z0, z1);
        float z2 = acc[nt][2] + bb0; z2 = 0.5f*z2*(1.f + erff(z2*0.7071067811865475f));
        float z3 = acc[nt][3] + bb1; z3 = 0.5f*z3*(1.f + erff(z3*0.7071067811865475f));
        hsh[(row+8)*36 + kp] = pk_hi(z2, z3);
        hsl[(row+8)*36 + kp] = pk_lo(z2, z3);
    }
    __syncthreads();

    // ---- GEMM2 (3xBF16) + residual ----
    float acc2[2][4];
    #pragma unroll
    for (int nt=0;nt<2;nt++){ acc2[nt][0]=0.f; acc2[nt][1]=0.f; acc2[nt][2]=0.f; acc2[nt][3]=0.f; }
    #pragma unroll
    for (int kt=0; kt<4; kt++){
        int ai = row*36 + kt*8 + (lane&3);
        uint32_t ah0=hsh[ai], ah1=hsh[ai+288], ah2=hsh[ai+4], ah3=hsh[ai+292];
        uint32_t al0=hsl[ai], al1=hsl[ai+288], al2=hsl[ai+4], al3=hsl[ai+292];
        int bi = (kt*8 + (lane&3))*72 + n0 + (lane>>2);
        #pragma unroll
        for (int nt=0; nt<2; nt++){
            uint32_t bh0=W2h[bi+nt*8], bh1=W2h[bi+nt*8+288];
            uint32_t bl0=W2l[bi+nt*8], bl1=W2l[bi+nt*8+288];
            MMA_BF16(acc2[nt], al0,al1,al2,al3, bh0,bh1);
            MMA_BF16(acc2[nt], ah0,ah1,ah2,ah3, bl0,bl1);
            MMA_BF16(acc2[nt], ah0,ah1,ah2,ah3, bh0,bh1);
        }
    }
    int gt = blockIdx.x*64 + row;
    #pragma unroll
    for (int nt=0; nt<2; nt++){
        int colg = n0 + nt*8 + 2*(lane&3);
        float bb0 = bs[64+colg], bb1 = bs[64+colg+1];
        float2 v0;
        v0.x = xs[row*68 + colg]     + acc2[nt][0] + bb0;
        v0.y = xs[row*68 + colg + 1] + acc2[nt][1] + bb1;
        *(float2*)(g_x + (size_t)gt*64 + colg) = v0;
        float2 v1;
        v1.x = xs[(row+8)*68 + colg]     + acc2[nt][2] + bb0;
        v1.y = xs[(row+8)*68 + colg + 1] + acc2[nt][3] + bb1;
        *(float2*)(g_x + (size_t)(gt+8)*64 + colg) = v1;
    }
}

// ============ 1x1 conv out + sigmoid ============
__global__ void k_out(const float* __restrict__ ow, const float* __restrict__ ob,
                      float* __restrict__ out){
    int id = blockIdx.x*256 + threadIdx.x;
    int t = id & (TT-1), b = id >> 12;
    const float4* xp = (const float4*)(g_x + (size_t)id*64);
    float a0 = __ldg(ob), a1 = __ldg(ob+1);
    #pragma unroll
    for (int d4=0; d4<16; d4++){
        float4 xv = xp[d4];
        a0 += xv.x*__ldg(ow+d4*4) + xv.y*__ldg(ow+d4*4+1) + xv.z*__ldg(ow+d4*4+2) + xv.w*__ldg(ow+d4*4+3);
        a1 += xv.x*__ldg(ow+64+d4*4) + xv.y*__ldg(ow+64+d4*4+1) + xv.z*__ldg(ow+64+d4*4+2) + xv.w*__ldg(ow+64+d4*4+3);
    }
    out[((size_t)(b*2))*TT + t]   = 1.f/(1.f+expf(-a0));
    out[((size_t)(b*2+1))*TT + t] = 1.f/(1.f+expf(-a1));
}

extern "C" void kernel_launch(void* const* d_in, const int* in_sizes, int n_in,
                              void* d_out, int out_size){
    const float* spec = (const float*)d_in[0];
    const float* c1w = (const float*)d_in[1];
    const float* c1b = (const float*)d_in[2];
    const float* c2w = (const float*)d_in[3];
    const float* c2b = (const float*)d_in[4];
    const float* c3w = (const float*)d_in[5];
    const float* c3b = (const float*)d_in[6];
    const float* Wq  = (const float*)d_in[7];
    const float* bq  = (const float*)d_in[8];
    const float* Wk  = (const float*)d_in[9];
    const float* bk  = (const float*)d_in[10];
    const float* Wv  = (const float*)d_in[11];
    const float* bv  = (const float*)d_in[12];
    const float* Er  = (const float*)d_in[13];
    const float* g1  = (const float*)d_in[14];
    const float* be1 = (const float*)d_in[15];
    const float* W1  = (const float*)d_in[16];
    const float* b1  = (const float*)d_in[17];
    const float* W2  = (const float*)d_in[18];
    const float* b2  = (const float*)d_in[19];
    const float* g2  = (const float*)d_in[20];
    const float* be2 = (const float*)d_in[21];
    const float* ow  = (const float*)d_in[22];
    const float* ob  = (const float*)d_in[23];

    const int SM_QKV    = (6400*2 + 4608*2)*4 + 192*4;      // 88832
    const int SM_ATTNFF = (2304*6)*4 + 4352*4 + 128*4;      // 73216

    cudaFuncSetAttribute(k_s2,  cudaFuncAttributeMaxDynamicSharedMemorySize, 65536);
    cudaFuncSetAttribute(k_s3,  cudaFuncAttributeMaxDynamicSharedMemorySize, 158208);
    cudaFuncSetAttribute(k_qkv, cudaFuncAttributeMaxDynamicSharedMemorySize, SM_QKV);
    cudaFuncSetAttribute(k_attnff, cudaFuncAttributeMaxDynamicSharedMemorySize, SM_ATTNFF);

    k_s1<<<3328, 256>>>(spec, c1w, c1b);
    k_s2<<<dim3(64,8), 256, 65536>>>(c2w, c2b);
    k_s3<<<dim3(32,8), 512, 158208>>>(c3w, c3b);
    for (int L=0; L<11; L++){
        k_qkv<<<256, 1024, SM_QKV>>>(Wq+L*4096, bq+L*64, Wk+L*4096, bk+L*64,
                                     Wv+L*4096, bv+L*64, g1+L*64, be1+L*64);
        k_attnff<<<512, 512, SM_ATTNFF>>>(Er+L*384, 1<<L,
                                          W1+L*4096, b1+L*64, W2+L*4096, b2+L*64,
                                          g2+L*64, be2+L*64);
    }
    k_out<<<128, 256>>>(ow, ob, (float*)d_out);
}

// round 14
// speedup vs baseline: 1.4220x; 1.0441x over previous
#include <cuda_runtime.h>
#include <cuda_bf16.h>
#include <math.h>
#include <stdint.h>

#define TT 4096
#define NB 8
#define NBT (NB*TT)

__device__ __align__(256) float g_s1[NB*208*TT];
__device__ __align__(256) float g_s2[NB*160*TT];
__device__ __align__(256) float g_x [NBT*64];
__device__ __align__(256) float g_q [NBT*64];
__device__ __align__(256) float g_k [NBT*64];
__device__ __align__(256) float g_v [NBT*64];

__device__ __forceinline__ uint32_t pk_hi(float a, float b){
    __nv_bfloat162 t; t.x = __float2bfloat16_rn(a); t.y = __float2bfloat16_rn(b);
    return *(uint32_t*)&t;
}
__device__ __forceinline__ uint32_t pk_lo(float a, float b){
    __nv_bfloat162 t;
    t.x = __float2bfloat16_rn(a - __bfloat162float(__float2bfloat16_rn(a)));
    t.y = __float2bfloat16_rn(b - __bfloat162float(__float2bfloat16_rn(b)));
    return *(uint32_t*)&t;
}
__device__ __forceinline__ void ldm4(uint32_t& r0, uint32_t& r1, uint32_t& r2, uint32_t& r3,
                                     const uint32_t* p){
    uint32_t a = (uint32_t)__cvta_generic_to_shared(p);
    asm volatile("ldmatrix.sync.aligned.m8n8.x4.shared.b16 {%0,%1,%2,%3}, [%4];"
        : "=r"(r0), "=r"(r1), "=r"(r2), "=r"(r3) : "r"(a));
}

#define MMA_BF16(d, a0,a1,a2,a3, b0,b1) \
  asm volatile("mma.sync.aligned.m16n8k16.row.col.f32.bf16.bf16.f32 " \
      "{%0,%1,%2,%3}, {%4,%5,%6,%7}, {%8,%9}, {%0,%1,%2,%3};" \
      : "+f"(d[0]), "+f"(d[1]), "+f"(d[2]), "+f"(d[3]) \
      : "r"(a0), "r"(a1), "r"(a2), "r"(a3), "r"(b0), "r"(b1))

// ============ stage 1: causal conv (1x3) + maxpool3(freq) + relu ============
__global__ void k_s1(const float* __restrict__ spec, const float* __restrict__ w,
                     const float* __restrict__ bias){
    int id = blockIdx.x*256 + threadIdx.x;
    int t  = id & (TT-1);
    int r  = id >> 12;
    int f2 = r % 26, b = r / 26;
    const float* sp = spec + (size_t)(b*81 + f2*3)*TT + t;
    float s[5][3];
    #pragma unroll
    for (int j=0;j<5;j++)
        #pragma unroll
        for (int i=0;i<3;i++)
            s[j][i] = (t+i < TT) ? sp[j*TT+i] : 0.f;
    #pragma unroll
    for (int c=0;c<8;c++){
        float a0=0.f,a1=0.f,a2=0.f;
        #pragma unroll
        for (int i=0;i<3;i++){
            if (t+i < TT){
                float w0=__ldg(w+(i*8+c)*3+0), w1=__ldg(w+(i*8+c)*3+1), w2=__ldg(w+(i*8+c)*3+2);
                float bb=__ldg(bias+i*8+c);
                a0 += bb + w0*s[0][i]+w1*s[1][i]+w2*s[2][i];
                a1 += bb + w0*s[1][i]+w1*s[2][i]+w2*s[3][i];
                a2 += bb + w0*s[2][i]+w1*s[3][i]+w2*s[4][i];
            }
        }
        float m = fmaxf(fmaxf(a0,a1),a2);
        g_s1[((size_t)(b*8+c)*26+f2)*TT + t] = fmaxf(m, 0.f);
    }
}

// ============ stage 2: conv (1x12) + maxpool3 + relu ============
__global__ void k_s2(const float* __restrict__ w2, const float* __restrict__ b2){
    extern __shared__ float sm[];
    float* s1s = sm;            // [208][64]
    float* ws  = sm + 208*64;   // 3072
    int tid = threadIdx.x, b = blockIdx.y, t0 = blockIdx.x*64;
    for (int i=tid; i<208*64; i+=256){
        int tl = i & 63, fr = i >> 6;
        s1s[i] = g_s1[((size_t)(b*208+fr))*TT + t0 + tl];
    }
    for (int i=tid; i<3072; i+=256) ws[i] = w2[i];
    __syncthreads();
    int tl = tid & 63, g = tid >> 6;
    for (int cb=0; cb<2; cb++){
        int co0 = g*8 + cb*4;
        float acc[4][5][3];
        #pragma unroll
        for (int u=0;u<4;u++){
            float bb = __ldg(b2 + co0 + u);
            #pragma unroll
            for (int f2=0;f2<5;f2++){ acc[u][f2][0]=bb; acc[u][f2][1]=bb; acc[u][f2][2]=bb; }
        }
        for (int cin=0; cin<8; cin++){
            float sv[26];
            #pragma unroll
            for (int ff=0; ff<26; ff++) sv[ff] = s1s[(cin*26+ff)*64 + tl];
            float w[4][12];
            #pragma unroll
            for (int u=0;u<4;u++)
                #pragma unroll
                for (int k=0;k<12;k++) w[u][k] = ws[(co0+u)*96 + cin*12 + k];
            #pragma unroll
            for (int f2=0; f2<5; f2++)
                #pragma unroll
                for (int k=0;k<12;k++)
                    #pragma unroll
                    for (int u=0;u<4;u++){
                        float wk = w[u][k];
                        acc[u][f2][0] += wk*sv[f2*3+k+0];
                        acc[u][f2][1] += wk*sv[f2*3+k+1];
                        acc[u][f2][2] += wk*sv[f2*3+k+2];
                    }
        }
        #pragma unroll
        for (int u=0;u<4;u++)
            #pragma unroll
            for (int f2=0;f2<5;f2++){
                float m = fmaxf(fmaxf(acc[u][f2][0],acc[u][f2][1]),acc[u][f2][2]);
                g_s2[((size_t)((b*32+co0+u)*5+f2))*TT + t0 + tl] = fmaxf(m, 0.f);
            }
    }
}

// ============ stage 3: causal conv (1x3, cin32,co64) + maxpool3 + relu ============
__global__ void __launch_bounds__(512) k_s3(const float* __restrict__ w3, const float* __restrict__ b3){
    extern __shared__ float sm[];
    float* s2s = sm;              // [160][132]
    float* w3s = sm + 160*132;    // 18432
    int tid = threadIdx.x, b = blockIdx.y, t0 = blockIdx.x*128;
    for (int i=tid; i<160*132; i+=512){
        int tl = i % 132, fr = i / 132;
        int tg = t0 + tl;
        s2s[i] = (tg < TT && tl < 130) ? g_s2[((size_t)(b*160+fr))*TT + tg] : 0.f;
    }
    for (int i=tid; i<18432; i+=512){
        int co = i & 63, r = i >> 6;
        int k = r % 3; r /= 3;
        int cin = r & 31, ii = r >> 5;
        w3s[i] = w3[((size_t)(ii*64+co)*32+cin)*3 + k];
    }
    __syncthreads();
    int co = tid & 63, tg8 = tid >> 6;
    float bb0 = __ldg(b3+co), bb1 = __ldg(b3+64+co), bb2 = __ldg(b3+128+co);
    for (int chunk=0; chunk<2; chunk++){
        int tlbase = tg8*16 + chunk*8;
        float acc[8][3];
        #pragma unroll
        for (int rr=0;rr<8;rr++){ acc[rr][0]=0.f; acc[rr][1]=0.f; acc[rr][2]=0.f; }
        for (int cin=0; cin<32; cin++){
            float sv[5][12];
            #pragma unroll
            for (int ff=0; ff<5; ff++){
                const float4* p = (const float4*)(s2s + (cin*5+ff)*132 + tlbase);
                float4 u0=p[0], u1=p[1], u2=p[2];
                sv[ff][0]=u0.x; sv[ff][1]=u0.y; sv[ff][2]=u0.z; sv[ff][3]=u0.w;
                sv[ff][4]=u1.x; sv[ff][5]=u1.y; sv[ff][6]=u1.z; sv[ff][7]=u1.w;
                sv[ff][8]=u2.x; sv[ff][9]=u2.y; sv[ff][10]=u2.z; sv[ff][11]=u2.w;
            }
            #pragma unroll
            for (int ii=0; ii<3; ii++)
                #pragma unroll
                for (int k=0; k<3; k++){
                    float wk = w3s[((ii*32+cin)*3+k)*64 + co];
                    #pragma unroll
                    for (int f=0; f<3; f++)
                        #pragma unroll
                        for (int rr=0; rr<8; rr++)
                            acc[rr][f] += wk*sv[f+k][rr+ii];
                }
        }
        #pragma unroll
        for (int rr=0; rr<8; rr++){
            int tg = t0 + tlbase + rr;
            float a0=acc[rr][0]+bb0, a1=acc[rr][1]+bb0, a2=acc[rr][2]+bb0;
            if (tg+1 < TT){ a0+=bb1; a1+=bb1; a2+=bb1; }
            if (tg+2 < TT){ a0+=bb2; a1+=bb2; a2+=bb2; }
            float m = fmaxf(fmaxf(a0,a1),a2);
            g_x[((size_t)(b*TT+tg))*64 + co] = fmaxf(m, 0.f);
        }
    }
}

// ============ LN1 + QKV via 3xBF16 mma, ldmatrix + frag-major B ============
// SMEM (u32): Whf[4][192][8], Wlf[...], Hh[128][36], Hl[128][36], bs float[192]
__global__ void __launch_bounds__(1024) k_qkv(
        const float* __restrict__ Wq, const float* __restrict__ bq,
        const float* __restrict__ Wk, const float* __restrict__ bk,
        const float* __restrict__ Wv, const float* __restrict__ bv,
        const float* __restrict__ gam, const float* __restrict__ bet){
    extern __shared__ char smraw[];
    uint32_t* Whf = (uint32_t*)smraw;       // 6144
    uint32_t* Wlf = Whf + 6144;             // 6144
    uint32_t* Hh  = Wlf + 6144;             // 4608
    uint32_t* Hl  = Hh + 4608;              // 4608
    float*    bs  = (float*)(Hl + 4608);    // 192
    int tid = threadIdx.x;

    // stage weights fragment-major: idx = kt*1536 + c*8 + j, j=(kp&3)*2+(kp>>2&1)
    for (int i=tid; i<6144; i+=1024){
        int kp = i & 31, c = i >> 5;
        int seg = c >> 6, cl = c & 63;
        const float* Wsrc = (seg==0) ? Wq : (seg==1) ? Wk : Wv;
        float w0 = Wsrc[cl*64 + 2*kp], w1 = Wsrc[cl*64 + 2*kp + 1];
        int kpl = kp & 7, kt = kp >> 3;
        int idx = kt*1536 + c*8 + (kpl&3)*2 + (kpl>>2);
        Whf[idx] = pk_hi(w0, w1);
        Wlf[idx] = pk_lo(w0, w1);
    }
    if (tid < 64){ bs[tid]=bq[tid]; bs[64+tid]=bk[tid]; bs[128+tid]=bv[tid]; }

    // LN1: 8 threads/token, 8 dims each -> 4 kpairs
    {
        int tok = tid >> 3, lane8 = tid & 7;
        int gtok = blockIdx.x*128 + tok;
        const float* xr = g_x + (size_t)gtok*64 + lane8*8;
        float4 u0 = *(const float4*)xr, u1 = *(const float4*)(xr+4);
        float v[8] = {u0.x,u0.y,u0.z,u0.w,u1.x,u1.y,u1.z,u1.w};
        float s=0.f, ss=0.f;
        #pragma unroll
        for (int m=0;m<8;m++){ s += v[m]; ss += v[m]*v[m]; }
        s += __shfl_xor_sync(0xffffffffu,s,1); ss += __shfl_xor_sync(0xffffffffu,ss,1);
        s += __shfl_xor_sync(0xffffffffu,s,2); ss += __shfl_xor_sync(0xffffffffu,ss,2);
        s += __shfl_xor_sync(0xffffffffu,s,4); ss += __shfl_xor_sync(0xffffffffu,ss,4);
        float mean = s*(1.f/64.f);
        float var  = ss*(1.f/64.f) - mean*mean;
        float rstd = rsqrtf(fmaxf(var,0.f) + 1e-5f);
        float h[8];
        #pragma unroll
        for (int m=0;m<8;m++){
            int dd = lane8*8+m;
            h[m] = (v[m]-mean)*rstd*__ldg(gam+dd) + __ldg(bet+dd);
        }
        #pragma unroll
        for (int j=0;j<4;j++){
            Hh[tok*36 + lane8*4 + j] = pk_hi(h[2*j], h[2*j+1]);
            Hl[tok*36 + lane8*4 + j] = pk_lo(h[2*j], h[2*j+1]);
        }
    }
    __syncthreads();

    // 32 warps = 8 m-groups (16 rows) x 4 n-groups (48 cols); K=64 = 4 kt of 16
    int lane = tid & 31, w = tid >> 5;
    int m0 = (w >> 2) << 4;
    int n0 = (w & 3) * 48;
    float acc[6][4];
    #pragma unroll
    for (int nt=0;nt<6;nt++){ acc[nt][0]=0.f; acc[nt][1]=0.f; acc[nt][2]=0.f; acc[nt][3]=0.f; }
    int row = m0 + (lane>>2);
    int arow = m0 + (lane & 7) + ((lane >> 3) & 1)*8;   // ldmatrix row
    int acolx = ((lane >> 4) & 1)*4;                     // ldmatrix col extra
    #pragma unroll
    for (int kt=0; kt<4; kt++){
        uint32_t ah0,ah1,ah2,ah3, al0,al1,al2,al3;
        ldm4(ah0,ah1,ah2,ah3, Hh + arow*36 + kt*8 + acolx);
        ldm4(al0,al1,al2,al3, Hl + arow*36 + kt*8 + acolx);
        int bbase = kt*1536 + (n0 + (lane>>2))*8 + (lane&3)*2;
        #pragma unroll
        for (int nt=0; nt<6; nt++){
            uint2 bh = *(const uint2*)(Whf + bbase + nt*64);
            uint2 bl = *(const uint2*)(Wlf + bbase + nt*64);
            MMA_BF16(acc[nt], al0,al1,al2,al3, bh.x,bh.y);
            MMA_BF16(acc[nt], ah0,ah1,ah2,ah3, bl.x,bl.y);
            MMA_BF16(acc[nt], ah0,ah1,ah2,ah3, bh.x,bh.y);
        }
    }
    int gt = blockIdx.x*128 + row;
    #pragma unroll
    for (int nt=0; nt<6; nt++){
        int colg = n0 + nt*8 + 2*(lane&3);
        int seg = colg >> 6, cl = colg & 63;
        float* dst = (seg==0) ? g_q : (seg==1) ? g_k : g_v;
        float b0 = bs[colg], b1 = bs[colg+1];
        float2 v0; v0.x = acc[nt][0] + b0; v0.y = acc[nt][1] + b1;
        *(float2*)(dst + (size_t)gt*64 + cl) = v0;
        float2 v1; v1.x = acc[nt][2] + b0; v1.y = acc[nt][3] + b1;
        *(float2*)(dst + (size_t)(gt+8)*64 + cl) = v1;
    }
}

// ============ attention + residual + LN2 + FF(3xBF16 mma) + residual (64 tok, 512 thr) ============
// SMEM (u32): W1hf[4][64][8] W1lf W2hf W2lf (2048 each), hsh[64][36] hsl, xs float[64][68], bs[128]
__global__ void __launch_bounds__(512, 2) k_attnff(
        const float* __restrict__ Er, int shift,
        const float* __restrict__ W1g, const float* __restrict__ b1p,
        const float* __restrict__ W2g, const float* __restrict__ b2p,
        const float* __restrict__ gam, const float* __restrict__ bet){
    extern __shared__ char smraw[];
    uint32_t* W1hf = (uint32_t*)smraw;       // 2048
    uint32_t* W1lf = W1hf + 2048;
    uint32_t* W2hf = W1lf + 2048;
    uint32_t* W2lf = W2hf + 2048;
    uint32_t* hsh  = W2lf + 2048;            // 2304 (64*36)
    uint32_t* hsl  = hsh + 2304;
    float*    xs   = (float*)(hsl + 2304);   // 4352 (64*68)
    float*    bs   = xs + 4352;              // 128
    int tid = threadIdx.x;

    for (int i=tid; i<2048; i+=512){
        int kp = i & 31, c = i >> 5;
        int kpl = kp & 7, kt = kp >> 3;
        int idx = kt*512 + c*8 + (kpl&3)*2 + (kpl>>2);
        float w0 = W1g[c*64 + 2*kp], w1 = W1g[c*64 + 2*kp + 1];
        W1hf[idx] = pk_hi(w0, w1);
        W1lf[idx] = pk_lo(w0, w1);
        w0 = W2g[c*64 + 2*kp]; w1 = W2g[c*64 + 2*kp + 1];
        W2hf[idx] = pk_hi(w0, w1);
        W2lf[idx] = pk_lo(w0, w1);
    }
    if (tid < 64){ bs[tid]=b1p[tid]; bs[64+tid]=b2p[tid]; }

    // ---- attention: 8 threads/token, 1 head each ----
    {
        int tok = tid >> 3, h = tid & 7;
        int gtok = blockIdx.x*64 + tok;
        int b = gtok >> 12, t = gtok & (TT-1);
        size_t bt = (size_t)b*TT + t;
        int sh[6]; sh[0]=0; sh[1]=0; sh[2]=shift; sh[3]=2*shift; sh[4]=3*shift; sh[5]=4*shift;
        const float* qp = g_q + bt*64 + h*8;
        float4 q0 = *(const float4*)qp, q1 = *(const float4*)(qp+4);
        float q[8] = {q0.x,q0.y,q0.z,q0.w,q1.x,q1.y,q1.z,q1.w};
        const float* er = Er + h*48;
        float lg[6];
        #pragma unroll
        for (int j=0;j<6;j++){
            float qe = 0.f;
            #pragma unroll
            for (int d=0;d<8;d++) qe += q[d]*__ldg(er + d*6 + j);
            lg[j] = qe;
        }
        #pragma unroll
        for (int j=0;j<6;j++){
            int tp = t - sh[j];
            float qk = 0.f;
            if (tp >= 0){
                const float* kp = g_k + ((size_t)b*TT+tp)*64 + h*8;
                float4 k0 = *(const float4*)kp, k1 = *(const float4*)(kp+4);
                qk = q[0]*k0.x + q[1]*k0.y + q[2]*k0.z + q[3]*k0.w
                   + q[4]*k1.x + q[5]*k1.y + q[6]*k1.z + q[7]*k1.w;
            }
            lg[j] = (qk + lg[j]) * 0.3535533905932738f;
        }
        float mx = lg[0];
        #pragma unroll
        for (int j=1;j<6;j++) mx = fmaxf(mx, lg[j]);
        float e[6], se = 0.f;
        #pragma unroll
        for (int j=0;j<6;j++){ e[j] = expf(lg[j]-mx); se += e[j]; }
        float inv = 1.f/se;
        float o[8] = {0,0,0,0,0,0,0,0};
        #pragma unroll
        for (int j=0;j<6;j++){
            int tp = t - sh[j];
            if (tp >= 0){
                const float* vp = g_v + ((size_t)b*TT+tp)*64 + h*8;
                float4 v0 = *(const float4*)vp, v1 = *(const float4*)(vp+4);
                float a = e[j];
                o[0]+=a*v0.x; o[1]+=a*v0.y; o[2]+=a*v0.z; o[3]+=a*v0.w;
                o[4]+=a*v1.x; o[5]+=a*v1.y; o[6]+=a*v1.z; o[7]+=a*v1.w;
            }
        }
        const float* xp = g_x + (size_t)gtok*64 + h*8;
        float4 x0 = *(const float4*)xp, x1 = *(const float4*)(xp+4);
        float* xd = xs + tok*68 + h*8;
        xd[0]=x0.x+o[0]*inv; xd[1]=x0.y+o[1]*inv; xd[2]=x0.z+o[2]*inv; xd[3]=x0.w+o[3]*inv;
        xd[4]=x1.x+o[4]*inv; xd[5]=x1.y+o[5]*inv; xd[6]=x1.z+o[6]*inv; xd[7]=x1.w+o[7]*inv;
    }
    __syncthreads();

    // ---- LN2: 8 threads/token, pack bf16 hi/lo ----
    {
        int tok = tid >> 3, lane8 = tid & 7;
        float v[8];
        #pragma unroll
        for (int m=0;m<8;m++) v[m] = xs[tok*68 + lane8*8 + m];
        float s=0.f, ss=0.f;
        #pragma unroll
        for (int m=0;m<8;m++){ s += v[m]; ss += v[m]*v[m]; }
        s += __shfl_xor_sync(0xffffffffu,s,1); ss += __shfl_xor_sync(0xffffffffu,ss,1);
        s += __shfl_xor_sync(0xffffffffu,s,2); ss += __shfl_xor_sync(0xffffffffu,ss,2);
        s += __shfl_xor_sync(0xffffffffu,s,4); ss += __shfl_xor_sync(0xffffffffu,ss,4);
        float mean = s*(1.f/64.f);
        float var  = ss*(1.f/64.f) - mean*mean;
        float rstd = rsqrtf(fmaxf(var,0.f) + 1e-5f);
        float h[8];
        #pragma unroll
        for (int m=0;m<8;m++){
            int dd = lane8*8+m;
            h[m] = (v[m]-mean)*rstd*__ldg(gam+dd) + __ldg(bet+dd);
        }
        #pragma unroll
        for (int j=0;j<4;j++){
            hsh[tok*36 + lane8*4 + j] = pk_hi(h[2*j], h[2*j+1]);
            hsl[tok*36 + lane8*4 + j] = pk_lo(h[2*j], h[2*j+1]);
        }
    }
    __syncthreads();

    // 16 warps = 4 m-groups (16 rows) x 4 n-groups (16 cols)
    int lane = tid & 31, w = tid >> 5;
    int m0 = (w >> 2) << 4;
    int n0 = (w & 3) * 16;
    int row = m0 + (lane>>2);
    int arow = m0 + (lane & 7) + ((lane >> 3) & 1)*8;
    int acolx = ((lane >> 4) & 1)*4;

    // ---- GEMM1 (3xBF16) ----
    float acc[2][4];
    #pragma unroll
    for (int nt=0;nt<2;nt++){ acc[nt][0]=0.f; acc[nt][1]=0.f; acc[nt][2]=0.f; acc[nt][3]=0.f; }
    #pragma unroll
    for (int kt=0; kt<4; kt++){
        uint32_t ah0,ah1,ah2,ah3, al0,al1,al2,al3;
        ldm4(ah0,ah1,ah2,ah3, hsh + arow*36 + kt*8 + acolx);
        ldm4(al0,al1,al2,al3, hsl + arow*36 + kt*8 + acolx);
        int bbase = kt*512 + (n0 + (lane>>2))*8 + (lane&3)*2;
        #pragma unroll
        for (int nt=0; nt<2; nt++){
            uint2 bh = *(const uint2*)(W1hf + bbase + nt*64);
            uint2 bl = *(const uint2*)(W1lf + bbase + nt*64);
            MMA_BF16(acc[nt], al0,al1,al2,al3, bh.x,bh.y);
            MMA_BF16(acc[nt], ah0,ah1,ah2,ah3, bl.x,bl.y);
            MMA_BF16(acc[nt], ah0,ah1,ah2,ah3, bh.x,bh.y);
        }
    }
    __syncthreads();
    // gelu -> repack as A for GEMM2 (col-pair == k-pair)
    #pragma unroll
    for (int nt=0; nt<2; nt++){
        int colg = n0 + nt*8 + 2*(lane&3);
        int kp = (colg >> 1);
        float bb0 = bs[colg], bb1 = bs[colg+1];
        float z0 = acc[nt][0] + bb0; z0 = 0.5f*z0*(1.f + erff(z0*0.7071067811865475f));
        float z1 = acc[nt][1] + bb1; z1 = 0.5f*z1*(1.f + erff(z1*0.7071067811865475f));
        hsh[row*36 + kp] = pk_hi(z0, z1);
        hsl[row*36 + kp] = pk_lo(z0, z1);
        float z2 = acc[nt][2] + bb0; z2 = 0.5f*z2*(1.f + erff(z2*0.7071067811865475f));
        float z3 = acc[nt][3] + bb1; z3 = 0.5f*z3*(1.f + erff(z3*0.7071067811865475f));
        hsh[(row+8)*36 + kp] = pk_hi(z2, z3);
        hsl[(row+8)*36 + kp] = pk_lo(z2, z3);
    }
    __syncthreads();

    // ---- GEMM2 (3xBF16) + residual ----
    float acc2[2][4];
    #pragma unroll
    for (int nt=0;nt<2;nt++){ acc2[nt][0]=0.f; acc2[nt][1]=0.f; acc2[nt][2]=0.f; acc2[nt][3]=0.f; }
    #pragma unroll
    for (int kt=0; kt<4; kt++){
        uint32_t ah0,ah1,ah2,ah3, al0,al1,al2,al3;
        ldm4(ah0,ah1,ah2,ah3, hsh + arow*36 + kt*8 + acolx);
        ldm4(al0,al1,al2,al3, hsl + arow*36 + kt*8 + acolx);
        int bbase = kt*512 + (n0 + (lane>>2))*8 + (lane&3)*2;
        #pragma unroll
        for (int nt=0; nt<2; nt++){
            uint2 bh = *(const uint2*)(W2hf + bbase + nt*64);
            uint2 bl = *(const uint2*)(W2lf + bbase + nt*64);
            MMA_BF16(acc2[nt], al0,al1,al2,al3, bh.x,bh.y);
            MMA_BF16(acc2[nt], ah0,ah1,ah2,ah3, bl.x,bl.y);
            MMA_BF16(acc2[nt], ah0,ah1,ah2,ah3, bh.x,bh.y);
        }
    }
    int gt = blockIdx.x*64 + row;
    #pragma unroll
    for (int nt=0; nt<2; nt++){
        int colg = n0 + nt*8 + 2*(lane&3);
        float bb0 = bs[64+colg], bb1 = bs[64+colg+1];
        float2 v0;
        v0.x = xs[row*68 + colg]     + acc2[nt][0] + bb0;
        v0.y = xs[row*68 + colg + 1] + acc2[nt][1] + bb1;
        *(float2*)(g_x + (size_t)gt*64 + colg) = v0;
        float2 v1;
        v1.x = xs[(row+8)*68 + colg]     + acc2[nt][2] + bb0;
        v1.y = xs[(row+8)*68 + colg + 1] + acc2[nt][3] + bb1;
        *(float2*)(g_x + (size_t)(gt+8)*64 + colg) = v1;
    }
}

// ============ 1x1 conv out + sigmoid ============
__global__ void k_out(const float* __restrict__ ow, const float* __restrict__ ob,
                      float* __restrict__ out){
    int id = blockIdx.x*256 + threadIdx.x;
    int t = id & (TT-1), b = id >> 12;
    const float4* xp = (const float4*)(g_x + (size_t)id*64);
    float a0 = __ldg(ob), a1 = __ldg(ob+1);
    #pragma unroll
    for (int d4=0; d4<16; d4++){
        float4 xv = xp[d4];
        a0 += xv.x*__ldg(ow+d4*4) + xv.y*__ldg(ow+d4*4+1) + xv.z*__ldg(ow+d4*4+2) + xv.w*__ldg(ow+d4*4+3);
        a1 += xv.x*__ldg(ow+64+d4*4) + xv.y*__ldg(ow+64+d4*4+1) + xv.z*__ldg(ow+64+d4*4+2) + xv.w*__ldg(ow+64+d4*4+3);
    }
    out[((size_t)(b*2))*TT + t]   = 1.f/(1.f+expf(-a0));
    out[((size_t)(b*2+1))*TT + t] = 1.f/(1.f+expf(-a1));
}

extern "C" void kernel_launch(void* const* d_in, const int* in_sizes, int n_in,
                              void* d_out, int out_size){
    const float* spec = (const float*)d_in[0];
    const float* c1w = (const float*)d_in[1];
    const float* c1b = (const float*)d_in[2];
    const float* c2w = (const float*)d_in[3];
    const float* c2b = (const float*)d_in[4];
    const float* c3w = (const float*)d_in[5];
    const float* c3b = (const float*)d_in[6];
    const float* Wq  = (const float*)d_in[7];
    const float* bq  = (const float*)d_in[8];
    const float* Wk  = (const float*)d_in[9];
    const float* bk  = (const float*)d_in[10];
    const float* Wv  = (const float*)d_in[11];
    const float* bv  = (const float*)d_in[12];
    const float* Er  = (const float*)d_in[13];
    const float* g1  = (const float*)d_in[14];
    const float* be1 = (const float*)d_in[15];
    const float* W1  = (const float*)d_in[16];
    const float* b1  = (const float*)d_in[17];
    const float* W2  = (const float*)d_in[18];
    const float* b2  = (const float*)d_in[19];
    const float* g2  = (const float*)d_in[20];
    const float* be2 = (const float*)d_in[21];
    const float* ow  = (const float*)d_in[22];
    const float* ob  = (const float*)d_in[23];

    const int SM_QKV    = (6144*2 + 4608*2)*4 + 192*4;      // 86784 + 768 = 86784? -> computed below
    const int SM_ATTNFF = (2048*4 + 2304*2)*4 + (4352+128)*4;

    cudaFuncSetAttribute(k_s2,  cudaFuncAttributeMaxDynamicSharedMemorySize, 65536);
    cudaFuncSetAttribute(k_s3,  cudaFuncAttributeMaxDynamicSharedMemorySize, 158208);
    cudaFuncSetAttribute(k_qkv, cudaFuncAttributeMaxDynamicSharedMemorySize, SM_QKV);
    cudaFuncSetAttribute(k_attnff, cudaFuncAttributeMaxDynamicSharedMemorySize, SM_ATTNFF);

    k_s1<<<3328, 256>>>(spec, c1w, c1b);
    k_s2<<<dim3(64,8), 256, 65536>>>(c2w, c2b);
    k_s3<<<dim3(32,8), 512, 158208>>>(c3w, c3b);
    for (int L=0; L<11; L++){
        k_qkv<<<256, 1024, SM_QKV>>>(Wq+L*4096, bq+L*64, Wk+L*4096, bk+L*64,
                                     Wv+L*4096, bv+L*64, g1+L*64, be1+L*64);
        k_attnff<<<512, 512, SM_ATTNFF>>>(Er+L*384, 1<<L,
                                          W1+L*4096, b1+L*64, W2+L*4096, b2+L*64,
                                          g2+L*64, be2+L*64);
    }
    k_out<<<128, 256>>>(ow, ob, (float*)d_out);
}

// round 15
// speedup vs baseline: 1.4598x; 1.0266x over previous
#include <cuda_runtime.h>
#include <cuda_bf16.h>
#include <math.h>
#include <stdint.h>

#define TT 4096
#define NB 8
#define NBT (NB*TT)

__device__ __align__(256) float g_s1[NB*208*TT];
__device__ __align__(256) float g_s2[NB*160*TT];
__device__ __align__(256) float g_x [NBT*64];
__device__ __align__(256) float g_q [NBT*64];
__device__ __align__(256) float g_k [NBT*64];
__device__ __align__(256) float g_v [NBT*64];

__device__ __forceinline__ uint32_t pk_hi(float a, float b){
    __nv_bfloat162 t; t.x = __float2bfloat16_rn(a); t.y = __float2bfloat16_rn(b);
    return *(uint32_t*)&t;
}
__device__ __forceinline__ uint32_t pk_lo(float a, float b){
    __nv_bfloat162 t;
    t.x = __float2bfloat16_rn(a - __bfloat162float(__float2bfloat16_rn(a)));
    t.y = __float2bfloat16_rn(b - __bfloat162float(__float2bfloat16_rn(b)));
    return *(uint32_t*)&t;
}
__device__ __forceinline__ void ldm4(uint32_t& r0, uint32_t& r1, uint32_t& r2, uint32_t& r3,
                                     const uint32_t* p){
    uint32_t a = (uint32_t)__cvta_generic_to_shared(p);
    asm volatile("ldmatrix.sync.aligned.m8n8.x4.shared.b16 {%0,%1,%2,%3}, [%4];"
        : "=r"(r0), "=r"(r1), "=r"(r2), "=r"(r3) : "r"(a));
}

#define MMA_BF16(d, a0,a1,a2,a3, b0,b1) \
  asm volatile("mma.sync.aligned.m16n8k16.row.col.f32.bf16.bf16.f32 " \
      "{%0,%1,%2,%3}, {%4,%5,%6,%7}, {%8,%9}, {%0,%1,%2,%3};" \
      : "+f"(d[0]), "+f"(d[1]), "+f"(d[2]), "+f"(d[3]) \
      : "r"(a0), "r"(a1), "r"(a2), "r"(a3), "r"(b0), "r"(b1))

// ---- packed fp32x2 helpers (Blackwell FFMA2) ----
__device__ __forceinline__ unsigned long long pk2(float x, float y){
    unsigned long long r;
    asm("mov.b64 %0, {%1,%2};" : "=l"(r) : "r"(__float_as_uint(x)), "r"(__float_as_uint(y)));
    return r;
}
__device__ __forceinline__ unsigned long long ffma2(unsigned long long a, unsigned long long b,
                                                    unsigned long long c){
    unsigned long long d;
    asm("fma.rn.f32x2 %0, %1, %2, %3;" : "=l"(d) : "l"(a), "l"(b), "l"(c));
    return d;
}
__device__ __forceinline__ void unpk(unsigned long long v, float& x, float& y){
    uint32_t lo, hi;
    asm("mov.b64 {%0,%1}, %2;" : "=r"(lo), "=r"(hi) : "l"(v));
    x = __uint_as_float(lo); y = __uint_as_float(hi);
}

// ============ stage 1: causal conv (1x3) + maxpool3(freq) + relu ============
__global__ void k_s1(const float* __restrict__ spec, const float* __restrict__ w,
                     const float* __restrict__ bias){
    int id = blockIdx.x*256 + threadIdx.x;
    int t  = id & (TT-1);
    int r  = id >> 12;
    int f2 = r % 26, b = r / 26;
    const float* sp = spec + (size_t)(b*81 + f2*3)*TT + t;
    float s[5][3];
    #pragma unroll
    for (int j=0;j<5;j++)
        #pragma unroll
        for (int i=0;i<3;i++)
            s[j][i] = (t+i < TT) ? sp[j*TT+i] : 0.f;
    #pragma unroll
    for (int c=0;c<8;c++){
        float a0=0.f,a1=0.f,a2=0.f;
        #pragma unroll
        for (int i=0;i<3;i++){
            if (t+i < TT){
                float w0=__ldg(w+(i*8+c)*3+0), w1=__ldg(w+(i*8+c)*3+1), w2=__ldg(w+(i*8+c)*3+2);
                float bb=__ldg(bias+i*8+c);
                a0 += bb + w0*s[0][i]+w1*s[1][i]+w2*s[2][i];
                a1 += bb + w0*s[1][i]+w1*s[2][i]+w2*s[3][i];
                a2 += bb + w0*s[2][i]+w1*s[3][i]+w2*s[4][i];
            }
        }
        float m = fmaxf(fmaxf(a0,a1),a2);
        g_s1[((size_t)(b*8+c)*26+f2)*TT + t] = fmaxf(m, 0.f);
    }
}

// ============ stage 2: conv (1x12) + maxpool3 + relu (FFMA2, co-pairs) ============
__global__ void __launch_bounds__(256, 2) k_s2(const float* __restrict__ w2, const float* __restrict__ b2){
    extern __shared__ float sm[];
    float* s1s = sm;            // [208][64]
    float* wsT = sm + 208*64;   // [96][32]  wsT[(cin*12+k)*32 + co]
    int tid = threadIdx.x, b = blockIdx.y, t0 = blockIdx.x*64;
    for (int i=tid; i<208*64; i+=256){
        int tl = i & 63, fr = i >> 6;
        s1s[i] = g_s1[((size_t)(b*208+fr))*TT + t0 + tl];
    }
    for (int i=tid; i<3072; i+=256){
        int co = i & 31, r = i >> 5;
        wsT[r*32 + co] = w2[co*96 + r];
    }
    __syncthreads();
    int tl = tid & 63, g = tid >> 6;
    for (int cb=0; cb<2; cb++){
        int co0 = g*8 + cb*4;
        unsigned long long acc2[2][5][3];
        #pragma unroll
        for (int pp=0;pp<2;pp++){
            unsigned long long bb = pk2(__ldg(b2+co0+2*pp), __ldg(b2+co0+2*pp+1));
            #pragma unroll
            for (int f2=0;f2<5;f2++){ acc2[pp][f2][0]=bb; acc2[pp][f2][1]=bb; acc2[pp][f2][2]=bb; }
        }
        for (int cin=0; cin<8; cin++){
            unsigned long long sv2[26];
            #pragma unroll
            for (int ff=0; ff<26; ff++){
                float s = s1s[(cin*26+ff)*64 + tl];
                sv2[ff] = pk2(s, s);
            }
            #pragma unroll
            for (int k=0;k<12;k++){
                const unsigned long long* wp =
                    (const unsigned long long*)(wsT + (cin*12+k)*32 + co0);
                unsigned long long w0 = wp[0], w1 = wp[1];
                #pragma unroll
                for (int f2=0; f2<5; f2++)
                    #pragma unroll
                    for (int p=0;p<3;p++){
                        unsigned long long s2v = sv2[f2*3+k+p];
                        acc2[0][f2][p] = ffma2(w0, s2v, acc2[0][f2][p]);
                        acc2[1][f2][p] = ffma2(w1, s2v, acc2[1][f2][p]);
                    }
            }
        }
        #pragma unroll
        for (int pp=0;pp<2;pp++)
            #pragma unroll
            for (int f2=0;f2<5;f2++){
                float lo0,hi0,lo1,hi1,lo2,hi2;
                unpk(acc2[pp][f2][0], lo0, hi0);
                unpk(acc2[pp][f2][1], lo1, hi1);
                unpk(acc2[pp][f2][2], lo2, hi2);
                float ml = fmaxf(fmaxf(lo0,lo1),lo2);
                float mh = fmaxf(fmaxf(hi0,hi1),hi2);
                size_t base = ((size_t)((b*32+co0+2*pp)*5+f2))*TT + t0 + tl;
                g_s2[base]        = fmaxf(ml, 0.f);
                g_s2[base + 5*TT] = fmaxf(mh, 0.f);
            }
    }
}

// ============ stage 3: causal conv (1x3, cin32,co64) + maxpool3 + relu (FFMA2, co-pairs) ============
__global__ void __launch_bounds__(512) k_s3(const float* __restrict__ w3, const float* __restrict__ b3){
    extern __shared__ float sm[];
    float* s2s = sm;              // [160][132]
    float* w3s = sm + 160*132;    // 18432, ((ii*32+cin)*3+k)*64 + co
    int tid = threadIdx.x, b = blockIdx.y, t0 = blockIdx.x*128;
    for (int i=tid; i<160*132; i+=512){
        int tl = i % 132, fr = i / 132;
        int tg = t0 + tl;
        s2s[i] = (tg < TT && tl < 130) ? g_s2[((size_t)(b*160+fr))*TT + tg] : 0.f;
    }
    for (int i=tid; i<18432; i+=512){
        int co = i & 63, r = i >> 6;
        int k = r % 3; r /= 3;
        int cin = r & 31, ii = r >> 5;
        w3s[i] = w3[((size_t)(ii*64+co)*32+cin)*3 + k];
    }
    __syncthreads();
    int co0 = (tid & 31)*2, tg8 = tid >> 5;   // 32 co-pairs x 16 t-groups
    float b0l=__ldg(b3+co0),     b0h=__ldg(b3+co0+1);
    float b1l=__ldg(b3+64+co0),  b1h=__ldg(b3+64+co0+1);
    float b2l=__ldg(b3+128+co0), b2h=__ldg(b3+128+co0+1);
    for (int chunk=0; chunk<2; chunk++){
        int tlbase = tg8*8 + chunk*4;
        unsigned long long acc2[4][3];
        #pragma unroll
        for (int rr=0;rr<4;rr++){ acc2[rr][0]=0ull; acc2[rr][1]=0ull; acc2[rr][2]=0ull; }
        for (int cin=0; cin<32; cin++){
            float sv[5][6];
            #pragma unroll
            for (int ff=0; ff<5; ff++){
                const float* p = s2s + (cin*5+ff)*132 + tlbase;
                float4 u0 = *(const float4*)p;
                float2 u1 = *(const float2*)(p+4);
                sv[ff][0]=u0.x; sv[ff][1]=u0.y; sv[ff][2]=u0.z; sv[ff][3]=u0.w;
                sv[ff][4]=u1.x; sv[ff][5]=u1.y;
            }
            #pragma unroll
            for (int ii=0; ii<3; ii++)
                #pragma unroll
                for (int k=0; k<3; k++){
                    unsigned long long wk2 =
                        *(const unsigned long long*)(w3s + ((ii*32+cin)*3+k)*64 + co0);
                    #pragma unroll
                    for (int f=0; f<3; f++){
                        int ff = f + k;
                        #pragma unroll
                        for (int rr=0; rr<4; rr++){
                            unsigned long long sb = pk2(sv[ff][rr+ii], sv[ff][rr+ii]);
                            acc2[rr][f] = ffma2(wk2, sb, acc2[rr][f]);
                        }
                    }
                }
        }
        #pragma unroll
        for (int rr=0; rr<4; rr++){
            int tg = t0 + tlbase + rr;
            float l0,h0,l1,h1,l2,h2;
            unpk(acc2[rr][0], l0, h0);
            unpk(acc2[rr][1], l1, h1);
            unpk(acc2[rr][2], l2, h2);
            float a0l=l0+b0l, a1l=l1+b0l, a2l=l2+b0l;
            float a0h=h0+b0h, a1h=h1+b0h, a2h=h2+b0h;
            if (tg+1 < TT){ a0l+=b1l; a1l+=b1l; a2l+=b1l; a0h+=b1h; a1h+=b1h; a2h+=b1h; }
            if (tg+2 < TT){ a0l+=b2l; a1l+=b2l; a2l+=b2l; a0h+=b2h; a1h+=b2h; a2h+=b2h; }
            float2 v;
            v.x = fmaxf(fmaxf(fmaxf(a0l,a1l),a2l), 0.f);
            v.y = fmaxf(fmaxf(fmaxf(a0h,a1h),a2h), 0.f);
            *(float2*)(g_x + ((size_t)(b*TT+tg))*64 + co0) = v;
        }
    }
}

// ============ LN1 + QKV via 3xBF16 mma, ldmatrix + frag-major B ============
__global__ void __launch_bounds__(1024) k_qkv(
        const float* __restrict__ Wq, const float* __restrict__ bq,
        const float* __restrict__ Wk, const float* __restrict__ bk,
        const float* __restrict__ Wv, const float* __restrict__ bv,
        const float* __restrict__ gam, const float* __restrict__ bet){
    extern __shared__ char smraw[];
    uint32_t* Whf = (uint32_t*)smraw;       // 6144
    uint32_t* Wlf = Whf + 6144;             // 6144
    uint32_t* Hh  = Wlf + 6144;             // 4608
    uint32_t* Hl  = Hh + 4608;              // 4608
    float*    bs  = (float*)(Hl + 4608);    // 192
    int tid = threadIdx.x;

    for (int i=tid; i<6144; i+=1024){
        int kp = i & 31, c = i >> 5;
        int seg = c >> 6, cl = c & 63;
        const float* Wsrc = (seg==0) ? Wq : (seg==1) ? Wk : Wv;
        float w0 = Wsrc[cl*64 + 2*kp], w1 = Wsrc[cl*64 + 2*kp + 1];
        int kpl = kp & 7, kt = kp >> 3;
        int idx = kt*1536 + c*8 + (kpl&3)*2 + (kpl>>2);
        Whf[idx] = pk_hi(w0, w1);
        Wlf[idx] = pk_lo(w0, w1);
    }
    if (tid < 64){ bs[tid]=bq[tid]; bs[64+tid]=bk[tid]; bs[128+tid]=bv[tid]; }

    {
        int tok = tid >> 3, lane8 = tid & 7;
        int gtok = blockIdx.x*128 + tok;
        const float* xr = g_x + (size_t)gtok*64 + lane8*8;
        float4 u0 = *(const float4*)xr, u1 = *(const float4*)(xr+4);
        float v[8] = {u0.x,u0.y,u0.z,u0.w,u1.x,u1.y,u1.z,u1.w};
        float s=0.f, ss=0.f;
        #pragma unroll
        for (int m=0;m<8;m++){ s += v[m]; ss += v[m]*v[m]; }
        s += __shfl_xor_sync(0xffffffffu,s,1); ss += __shfl_xor_sync(0xffffffffu,ss,1);
        s += __shfl_xor_sync(0xffffffffu,s,2); ss += __shfl_xor_sync(0xffffffffu,ss,2);
        s += __shfl_xor_sync(0xffffffffu,s,4); ss += __shfl_xor_sync(0xffffffffu,ss,4);
        float mean = s*(1.f/64.f);
        float var  = ss*(1.f/64.f) - mean*mean;
        float rstd = rsqrtf(fmaxf(var,0.f) + 1e-5f);
        float h[8];
        #pragma unroll
        for (int m=0;m<8;m++){
            int dd = lane8*8+m;
            h[m] = (v[m]-mean)*rstd*__ldg(gam+dd) + __ldg(bet+dd);
        }
        #pragma unroll
        for (int j=0;j<4;j++){
            Hh[tok*36 + lane8*4 + j] = pk_hi(h[2*j], h[2*j+1]);
            Hl[tok*36 + lane8*4 + j] = pk_lo(h[2*j], h[2*j+1]);
        }
    }
    __syncthreads();

    int lane = tid & 31, w = tid >> 5;
    int m0 = (w >> 2) << 4;
    int n0 = (w & 3) * 48;
    float acc[6][4];
    #pragma unroll
    for (int nt=0;nt<6;nt++){ acc[nt][0]=0.f; acc[nt][1]=0.f; acc[nt][2]=0.f; acc[nt][3]=0.f; }
    int row = m0 + (lane>>2);
    int arow = m0 + (lane & 7) + ((lane >> 3) & 1)*8;
    int acolx = ((lane >> 4) & 1)*4;
    #pragma unroll
    for (int kt=0; kt<4; kt++){
        uint32_t ah0,ah1,ah2,ah3, al0,al1,al2,al3;
        ldm4(ah0,ah1,ah2,ah3, Hh + arow*36 + kt*8 + acolx);
        ldm4(al0,al1,al2,al3, Hl + arow*36 + kt*8 + acolx);
        int bbase = kt*1536 + (n0 + (lane>>2))*8 + (lane&3)*2;
        #pragma unroll
        for (int nt=0; nt<6; nt++){
            uint2 bh = *(const uint2*)(Whf + bbase + nt*64);
            uint2 bl = *(const uint2*)(Wlf + bbase + nt*64);
            MMA_BF16(acc[nt], al0,al1,al2,al3, bh.x,bh.y);
            MMA_BF16(acc[nt], ah0,ah1,ah2,ah3, bl.x,bl.y);
            MMA_BF16(acc[nt], ah0,ah1,ah2,ah3, bh.x,bh.y);
        }
    }
    int gt = blockIdx.x*128 + row;
    #pragma unroll
    for (int nt=0; nt<6; nt++){
        int colg = n0 + nt*8 + 2*(lane&3);
        int seg = colg >> 6, cl = colg & 63;
        float* dst = (seg==0) ? g_q : (seg==1) ? g_k : g_v;
        float b0 = bs[colg], b1 = bs[colg+1];
        float2 v0; v0.x = acc[nt][0] + b0; v0.y = acc[nt][1] + b1;
        *(float2*)(dst + (size_t)gt*64 + cl) = v0;
        float2 v1; v1.x = acc[nt][2] + b0; v1.y = acc[nt][3] + b1;
        *(float2*)(dst + (size_t)(gt+8)*64 + cl) = v1;
    }
}

// ============ attention + residual + LN2 + FF(3xBF16 mma) + residual ============
__global__ void __launch_bounds__(512, 2) k_attnff(
        const float* __restrict__ Er, int shift,
        const float* __restrict__ W1g, const float* __restrict__ b1p,
        const float* __restrict__ W2g, const float* __restrict__ b2p,
        const float* __restrict__ gam, const float* __restrict__ bet){
    extern __shared__ char smraw[];
    uint32_t* W1hf = (uint32_t*)smraw;       // 2048
    uint32_t* W1lf = W1hf + 2048;
    uint32_t* W2hf = W1lf + 2048;
    uint32_t* W2lf = W2hf + 2048;
    uint32_t* hsh  = W2lf + 2048;            // 2304
    uint32_t* hsl  = hsh + 2304;
    float*    xs   = (float*)(hsl + 2304);   // 4352
    float*    bs   = xs + 4352;              // 128
    int tid = threadIdx.x;

    for (int i=tid; i<2048; i+=512){
        int kp = i & 31, c = i >> 5;
        int kpl = kp & 7, kt = kp >> 3;
        int idx = kt*512 + c*8 + (kpl&3)*2 + (kpl>>2);
        float w0 = W1g[c*64 + 2*kp], w1 = W1g[c*64 + 2*kp + 1];
        W1hf[idx] = pk_hi(w0, w1);
        W1lf[idx] = pk_lo(w0, w1);
        w0 = W2g[c*64 + 2*kp]; w1 = W2g[c*64 + 2*kp + 1];
        W2hf[idx] = pk_hi(w0, w1);
        W2lf[idx] = pk_lo(w0, w1);
    }
    if (tid < 64){ bs[tid]=b1p[tid]; bs[64+tid]=b2p[tid]; }

    {
        int tok = tid >> 3, h = tid & 7;
        int gtok = blockIdx.x*64 + tok;
        int b = gtok >> 12, t = gtok & (TT-1);
        size_t bt = (size_t)b*TT + t;
        int sh[6]; sh[0]=0; sh[1]=0; sh[2]=shift; sh[3]=2*shift; sh[4]=3*shift; sh[5]=4*shift;
        const float* qp = g_q + bt*64 + h*8;
        float4 q0 = *(const float4*)qp, q1 = *(const float4*)(qp+4);
        float q[8] = {q0.x,q0.y,q0.z,q0.w,q1.x,q1.y,q1.z,q1.w};
        const float* er = Er + h*48;
        float lg[6];
        #pragma unroll
        for (int j=0;j<6;j++){
            float qe = 0.f;
            #pragma unroll
            for (int d=0;d<8;d++) qe += q[d]*__ldg(er + d*6 + j);
            lg[j] = qe;
        }
        #pragma unroll
        for (int j=0;j<6;j++){
            int tp = t - sh[j];
            float qk = 0.f;
            if (tp >= 0){
                const float* kp = g_k + ((size_t)b*TT+tp)*64 + h*8;
                float4 k0 = *(const float4*)kp, k1 = *(const float4*)(kp+4);
                qk = q[0]*k0.x + q[1]*k0.y + q[2]*k0.z + q[3]*k0.w
                   + q[4]*k1.x + q[5]*k1.y + q[6]*k1.z + q[7]*k1.w;
            }
            lg[j] = (qk + lg[j]) * 0.3535533905932738f;
        }
        float mx = lg[0];
        #pragma unroll
        for (int j=1;j<6;j++) mx = fmaxf(mx, lg[j]);
        float e[6], se = 0.f;
        #pragma unroll
        for (int j=0;j<6;j++){ e[j] = expf(lg[j]-mx); se += e[j]; }
        float inv = 1.f/se;
        float o[8] = {0,0,0,0,0,0,0,0};
        #pragma unroll
        for (int j=0;j<6;j++){
            int tp = t - sh[j];
            if (tp >= 0){
                const float* vp = g_v + ((size_t)b*TT+tp)*64 + h*8;
                float4 v0 = *(const float4*)vp, v1 = *(const float4*)(vp+4);
                float a = e[j];
                o[0]+=a*v0.x; o[1]+=a*v0.y; o[2]+=a*v0.z; o[3]+=a*v0.w;
                o[4]+=a*v1.x; o[5]+=a*v1.y; o[6]+=a*v1.z; o[7]+=a*v1.w;
            }
        }
        const float* xp = g_x + (size_t)gtok*64 + h*8;
        float4 x0 = *(const float4*)xp, x1 = *(const float4*)(xp+4);
        float* xd = xs + tok*68 + h*8;
        xd[0]=x0.x+o[0]*inv; xd[1]=x0.y+o[1]*inv; xd[2]=x0.z+o[2]*inv; xd[3]=x0.w+o[3]*inv;
        xd[4]=x1.x+o[4]*inv; xd[5]=x1.y+o[5]*inv; xd[6]=x1.z+o[6]*inv; xd[7]=x1.w+o[7]*inv;
    }
    __syncthreads();

    {
        int tok = tid >> 3, lane8 = tid & 7;
        float v[8];
        #pragma unroll
        for (int m=0;m<8;m++) v[m] = xs[tok*68 + lane8*8 + m];
        float s=0.f, ss=0.f;
        #pragma unroll
        for (int m=0;m<8;m++){ s += v[m]; ss += v[m]*v[m]; }
        s += __shfl_xor_sync(0xffffffffu,s,1); ss += __shfl_xor_sync(0xffffffffu,ss,1);
        s += __shfl_xor_sync(0xffffffffu,s,2); ss += __shfl_xor_sync(0xffffffffu,ss,2);
        s += __shfl_xor_sync(0xffffffffu,s,4); ss += __shfl_xor_sync(0xffffffffu,ss,4);
        float mean = s*(1.f/64.f);
        float var  = ss*(1.f/64.f) - mean*mean;
        float rstd = rsqrtf(fmaxf(var,0.f) + 1e-5f);
        float h[8];
        #pragma unroll
        for (int m=0;m<8;m++){
            int dd = lane8*8+m;
            h[m] = (v[m]-mean)*rstd*__ldg(gam+dd) + __ldg(bet+dd);
        }
        #pragma unroll
        for (int j=0;j<4;j++){
            hsh[tok*36 + lane8*4 + j] = pk_hi(h[2*j], h[2*j+1]);
            hsl[tok*36 + lane8*4 + j] = pk_lo(h[2*j], h[2*j+1]);
        }
    }
    __syncthreads();

    int lane = tid & 31, w = tid >> 5;
    int m0 = (w >> 2) << 4;
    int n0 = (w & 3) * 16;
    int row = m0 + (lane>>2);
    int arow = m0 + (lane & 7) + ((lane >> 3) & 1)*8;
    int acolx = ((lane >> 4) & 1)*4;

    float acc[2][4];
    #pragma unroll
    for (int nt=0;nt<2;nt++){ acc[nt][0]=0.f; acc[nt][1]=0.f; acc[nt][2]=0.f; acc[nt][3]=0.f; }
    #pragma unroll
    for (int kt=0; kt<4; kt++){
        uint32_t ah0,ah1,ah2,ah3, al0,al1,al2,al3;
        ldm4(ah0,ah1,ah2,ah3, hsh + arow*36 + kt*8 + acolx);
        ldm4(al0,al1,al2,al3, hsl + arow*36 + kt*8 + acolx);
        int bbase = kt*512 + (n0 + (lane>>2))*8 + (lane&3)*2;
        #pragma unroll
        for (int nt=0; nt<2; nt++){
            uint2 bh = *(const uint2*)(W1hf + bbase + nt*64);
            uint2 bl = *(const uint2*)(W1lf + bbase + nt*64);
            MMA_BF16(acc[nt], al0,al1,al2,al3, bh.x,bh.y);
            MMA_BF16(acc[nt], ah0,ah1,ah2,ah3, bl.x,bl.y);
            MMA_BF16(acc[nt], ah0,ah1,ah2,ah3, bh.x,bh.y);
        }
    }
    __syncthreads();
    #pragma unroll
    for (int nt=0; nt<2; nt++){
        int colg = n0 + nt*8 + 2*(lane&3);
        int kp = (colg >> 1);
        float bb0 = bs[colg], bb1 = bs[colg+1];
        float z0 = acc[nt][0] + bb0; z0 = 0.5f*z0*(1.f + erff(z0*0.7071067811865475f));
        float z1 = acc[nt][1] + bb1; z1 = 0.5f*z1*(1.f + erff(z1*0.7071067811865475f));
        hsh[row*36 + kp] = pk_hi(z0, z1);
        hsl[row*36 + kp] = pk_lo(z0, z1);
        float z2 = acc[nt][2] + bb0; z2 = 0.5f*z2*(1.f + erff(z2*0.7071067811865475f));
        float z3 = acc[nt][3] + bb1; z3 = 0.5f*z3*(1.f + erff(z3*0.7071067811865475f));
        hsh[(row+8)*36 + kp] = pk_hi(z2, z3);
        hsl[(row+8)*36 + kp] = pk_lo(z2, z3);
    }
    __syncthreads();

    float acc2[2][4];
    #pragma unroll
    for (int nt=0;nt<2;nt++){ acc2[nt][0]=0.f; acc2[nt][1]=0.f; acc2[nt][2]=0.f; acc2[nt][3]=0.f; }
    #pragma unroll
    for (int kt=0; kt<4; kt++){
        uint32_t ah0,ah1,ah2,ah3, al0,al1,al2,al3;
        ldm4(ah0,ah1,ah2,ah3, hsh + arow*36 + kt*8 + acolx);
        ldm4(al0,al1,al2,al3, hsl + arow*36 + kt*8 + acolx);
        int bbase = kt*512 + (n0 + (lane>>2))*8 + (lane&3)*2;
        #pragma unroll
        for (int nt=0; nt<2; nt++){
            uint2 bh = *(const uint2*)(W2hf + bbase + nt*64);
            uint2 bl = *(const uint2*)(W2lf + bbase + nt*64);
            MMA_BF16(acc2[nt], al0,al1,al2,al3, bh.x,bh.y);
            MMA_BF16(acc2[nt], ah0,ah1,ah2,ah3, bl.x,bl.y);
            MMA_BF16(acc2[nt], ah0,ah1,ah2,ah3, bh.x,bh.y);
        }
    }
    int gt = blockIdx.x*64 + row;
    #pragma unroll
    for (int nt=0; nt<2; nt++){
        int colg = n0 + nt*8 + 2*(lane&3);
        float bb0 = bs[64+colg], bb1 = bs[64+colg+1];
        float2 v0;
        v0.x = xs[row*68 + colg]     + acc2[nt][0] + bb0;
        v0.y = xs[row*68 + colg + 1] + acc2[nt][1] + bb1;
        *(float2*)(g_x + (size_t)gt*64 + colg) = v0;
        float2 v1;
        v1.x = xs[(row+8)*68 + colg]     + acc2[nt][2] + bb0;
        v1.y = xs[(row+8)*68 + colg + 1] + acc2[nt][3] + bb1;
        *(float2*)(g_x + (size_t)(gt+8)*64 + colg) = v1;
    }
}

// ============ 1x1 conv out + sigmoid ============
__global__ void k_out(const float* __restrict__ ow, const float* __restrict__ ob,
                      float* __restrict__ out){
    int id = blockIdx.x*256 + threadIdx.x;
    int t = id & (TT-1), b = id >> 12;
    const float4* xp = (const float4*)(g_x + (size_t)id*64);
    float a0 = __ldg(ob), a1 = __ldg(ob+1);
    #pragma unroll
    for (int d4=0; d4<16; d4++){
        float4 xv = xp[d4];
        a0 += xv.x*__ldg(ow+d4*4) + xv.y*__ldg(ow+d4*4+1) + xv.z*__ldg(ow+d4*4+2) + xv.w*__ldg(ow+d4*4+3);
        a1 += xv.x*__ldg(ow+64+d4*4) + xv.y*__ldg(ow+64+d4*4+1) + xv.z*__ldg(ow+64+d4*4+2) + xv.w*__ldg(ow+64+d4*4+3);
    }
    out[((size_t)(b*2))*TT + t]   = 1.f/(1.f+expf(-a0));
    out[((size_t)(b*2+1))*TT + t] = 1.f/(1.f+expf(-a1));
}

extern "C" void kernel_launch(void* const* d_in, const int* in_sizes, int n_in,
                              void* d_out, int out_size){
    const float* spec = (const float*)d_in[0];
    const float* c1w = (const float*)d_in[1];
    const float* c1b = (const float*)d_in[2];
    const float* c2w = (const float*)d_in[3];
    const float* c2b = (const float*)d_in[4];
    const float* c3w = (const float*)d_in[5];
    const float* c3b = (const float*)d_in[6];
    const float* Wq  = (const float*)d_in[7];
    const float* bq  = (const float*)d_in[8];
    const float* Wk  = (const float*)d_in[9];
    const float* bk  = (const float*)d_in[10];
    const float* Wv  = (const float*)d_in[11];
    const float* bv  = (const float*)d_in[12];
    const float* Er  = (const float*)d_in[13];
    const float* g1  = (const float*)d_in[14];
    const float* be1 = (const float*)d_in[15];
    const float* W1  = (const float*)d_in[16];
    const float* b1  = (const float*)d_in[17];
    const float* W2  = (const float*)d_in[18];
    const float* b2  = (const float*)d_in[19];
    const float* g2  = (const float*)d_in[20];
    const float* be2 = (const float*)d_in[21];
    const float* ow  = (const float*)d_in[22];
    const float* ob  = (const float*)d_in[23];

    const int SM_QKV    = (6144*2 + 4608*2)*4 + 192*4;          // 86784
    const int SM_ATTNFF = (2048*4 + 2304*2)*4 + (4352+128)*4;   // 69120

    cudaFuncSetAttribute(k_s2,  cudaFuncAttributeMaxDynamicSharedMemorySize, 65536);
    cudaFuncSetAttribute(k_s3,  cudaFuncAttributeMaxDynamicSharedMemorySize, 158208);
    cudaFuncSetAttribute(k_qkv, cudaFuncAttributeMaxDynamicSharedMemorySize, SM_QKV);
    cudaFuncSetAttribute(k_attnff, cudaFuncAttributeMaxDynamicSharedMemorySize, SM_ATTNFF);

    k_s1<<<3328, 256>>>(spec, c1w, c1b);
    k_s2<<<dim3(64,8), 256, 65536>>>(c2w, c2b);
    k_s3<<<dim3(32,8), 512, 158208>>>(c3w, c3b);
    for (int L=0; L<11; L++){
        k_qkv<<<256, 1024, SM_QKV>>>(Wq+L*4096, bq+L*64, Wk+L*4096, bk+L*64,
                                     Wv+L*4096, bv+L*64, g1+L*64, be1+L*64);
        k_attnff<<<512, 512, SM_ATTNFF>>>(Er+L*384, 1<<L,
                                          W1+L*4096, b1+L*64, W2+L*4096, b2+L*64,
                                          g2+L*64, be2+L*64);
    }
    k_out<<<128, 256>>>(ow, ob, (float*)d_out);
}

// round 16
// speedup vs baseline: 1.5591x; 1.0680x over previous
#include <cuda_runtime.h>
#include <cuda_bf16.h>
#include <math.h>
#include <stdint.h>

#define TT 4096
#define NB 8
#define NBT (NB*TT)

__device__ __align__(256) float g_s1[NB*208*TT];
__device__ __align__(256) float g_s2[NB*160*TT];
__device__ __align__(256) float g_x [NBT*64];
__device__ __align__(256) float g_q [NBT*64];
__device__ __align__(256) float g_k [NBT*64];
__device__ __align__(256) float g_v [NBT*64];

__device__ __forceinline__ uint32_t pk_hi(float a, float b){
    __nv_bfloat162 t; t.x = __float2bfloat16_rn(a); t.y = __float2bfloat16_rn(b);
    return *(uint32_t*)&t;
}
__device__ __forceinline__ uint32_t pk_lo(float a, float b){
    __nv_bfloat162 t;
    t.x = __float2bfloat16_rn(a - __bfloat162float(__float2bfloat16_rn(a)));
    t.y = __float2bfloat16_rn(b - __bfloat162float(__float2bfloat16_rn(b)));
    return *(uint32_t*)&t;
}
__device__ __forceinline__ void ldm4(uint32_t& r0, uint32_t& r1, uint32_t& r2, uint32_t& r3,
                                     const uint32_t* p){
    uint32_t a = (uint32_t)__cvta_generic_to_shared(p);
    asm volatile("ldmatrix.sync.aligned.m8n8.x4.shared.b16 {%0,%1,%2,%3}, [%4];"
        : "=r"(r0), "=r"(r1), "=r"(r2), "=r"(r3) : "r"(a));
}

#define MMA_BF16(d, a0,a1,a2,a3, b0,b1) \
  asm volatile("mma.sync.aligned.m16n8k16.row.col.f32.bf16.bf16.f32 " \
      "{%0,%1,%2,%3}, {%4,%5,%6,%7}, {%8,%9}, {%0,%1,%2,%3};" \
      : "+f"(d[0]), "+f"(d[1]), "+f"(d[2]), "+f"(d[3]) \
      : "r"(a0), "r"(a1), "r"(a2), "r"(a3), "r"(b0), "r"(b1))

// ---- packed fp32x2 helpers (Blackwell FFMA2) ----
__device__ __forceinline__ unsigned long long pk2(float x, float y){
    unsigned long long r;
    asm("mov.b64 %0, {%1,%2};" : "=l"(r) : "r"(__float_as_uint(x)), "r"(__float_as_uint(y)));
    return r;
}
__device__ __forceinline__ unsigned long long ffma2(unsigned long long a, unsigned long long b,
                                                    unsigned long long c){
    unsigned long long d;
    asm("fma.rn.f32x2 %0, %1, %2, %3;" : "=l"(d) : "l"(a), "l"(b), "l"(c));
    return d;
}
__device__ __forceinline__ void unpk(unsigned long long v, float& x, float& y){
    uint32_t lo, hi;
    asm("mov.b64 {%0,%1}, %2;" : "=r"(lo), "=r"(hi) : "l"(v));
    x = __uint_as_float(lo); y = __uint_as_float(hi);
}

// ============ stage 1: causal conv (1x3) + maxpool3(freq) + relu (FFMA2 ch-pairs) ============
__global__ void k_s1(const float* __restrict__ spec, const float* __restrict__ w,
                     const float* __restrict__ bias){
    int id = blockIdx.x*256 + threadIdx.x;
    int t  = id & (TT-1);
    int r  = id >> 12;
    int f2 = r % 26, b = r / 26;
    const float* sp = spec + (size_t)(b*81 + f2*3)*TT + t;
    float s[5][3];
    #pragma unroll
    for (int j=0;j<5;j++)
        #pragma unroll
        for (int i=0;i<3;i++)
            s[j][i] = (t+i < TT) ? sp[j*TT+i] : 0.f;
    unsigned long long sb[5][3];
    #pragma unroll
    for (int j=0;j<5;j++)
        #pragma unroll
        for (int i=0;i<3;i++)
            sb[j][i] = pk2(s[j][i], s[j][i]);
    int nv = (TT - t < 3) ? (TT - t) : 3;
    #pragma unroll
    for (int cp=0; cp<4; cp++){
        int c0 = cp*2;
        unsigned long long a0=0ull, a1=0ull, a2=0ull;
        #pragma unroll
        for (int i=0;i<3;i++){
            if (t+i < TT){
                unsigned long long w0 = pk2(__ldg(w+(i*8+c0)*3+0), __ldg(w+(i*8+c0+1)*3+0));
                unsigned long long w1 = pk2(__ldg(w+(i*8+c0)*3+1), __ldg(w+(i*8+c0+1)*3+1));
                unsigned long long w2 = pk2(__ldg(w+(i*8+c0)*3+2), __ldg(w+(i*8+c0+1)*3+2));
                a0 = ffma2(w0, sb[0][i], a0); a0 = ffma2(w1, sb[1][i], a0); a0 = ffma2(w2, sb[2][i], a0);
                a1 = ffma2(w0, sb[1][i], a1); a1 = ffma2(w1, sb[2][i], a1); a1 = ffma2(w2, sb[3][i], a1);
                a2 = ffma2(w0, sb[2][i], a2); a2 = ffma2(w1, sb[3][i], a2); a2 = ffma2(w2, sb[4][i], a2);
            }
        }
        float bb0 = 0.f, bb1 = 0.f;
        #pragma unroll
        for (int i=0;i<3;i++){
            if (i < nv){ bb0 += __ldg(bias+i*8+c0); bb1 += __ldg(bias+i*8+c0+1); }
        }
        float l0,h0,l1,h1,l2,h2;
        unpk(a0,l0,h0); unpk(a1,l1,h1); unpk(a2,l2,h2);
        float ml = fmaxf(fmaxf(l0+bb0, l1+bb0), l2+bb0);
        float mh = fmaxf(fmaxf(h0+bb1, h1+bb1), h2+bb1);
        g_s1[((size_t)(b*8+c0)*26+f2)*TT + t]     = fmaxf(ml, 0.f);
        g_s1[((size_t)(b*8+c0+1)*26+f2)*TT + t]   = fmaxf(mh, 0.f);
    }
}

// ============ stage 2: conv (1x12) + maxpool3 + relu (FFMA2, co-pairs) ============
__global__ void __launch_bounds__(256, 2) k_s2(const float* __restrict__ w2, const float* __restrict__ b2){
    extern __shared__ float sm[];
    float* s1s = sm;            // [208][64]
    float* wsT = sm + 208*64;   // [96][32]
    int tid = threadIdx.x, b = blockIdx.y, t0 = blockIdx.x*64;
    for (int i=tid; i<208*64; i+=256){
        int tl = i & 63, fr = i >> 6;
        s1s[i] = g_s1[((size_t)(b*208+fr))*TT + t0 + tl];
    }
    for (int i=tid; i<3072; i+=256){
        int co = i & 31, r = i >> 5;
        wsT[r*32 + co] = w2[co*96 + r];
    }
    __syncthreads();
    int tl = tid & 63, g = tid >> 6;
    for (int cb=0; cb<2; cb++){
        int co0 = g*8 + cb*4;
        unsigned long long acc2[2][5][3];
        #pragma unroll
        for (int pp=0;pp<2;pp++){
            unsigned long long bb = pk2(__ldg(b2+co0+2*pp), __ldg(b2+co0+2*pp+1));
            #pragma unroll
            for (int f2=0;f2<5;f2++){ acc2[pp][f2][0]=bb; acc2[pp][f2][1]=bb; acc2[pp][f2][2]=bb; }
        }
        for (int cin=0; cin<8; cin++){
            unsigned long long sv2[26];
            #pragma unroll
            for (int ff=0; ff<26; ff++){
                float s = s1s[(cin*26+ff)*64 + tl];
                sv2[ff] = pk2(s, s);
            }
            #pragma unroll
            for (int k=0;k<12;k++){
                const unsigned long long* wp =
                    (const unsigned long long*)(wsT + (cin*12+k)*32 + co0);
                unsigned long long w0 = wp[0], w1 = wp[1];
                #pragma unroll
                for (int f2=0; f2<5; f2++)
                    #pragma unroll
                    for (int p=0;p<3;p++){
                        unsigned long long s2v = sv2[f2*3+k+p];
                        acc2[0][f2][p] = ffma2(w0, s2v, acc2[0][f2][p]);
                        acc2[1][f2][p] = ffma2(w1, s2v, acc2[1][f2][p]);
                    }
            }
        }
        #pragma unroll
        for (int pp=0;pp<2;pp++)
            #pragma unroll
            for (int f2=0;f2<5;f2++){
                float lo0,hi0,lo1,hi1,lo2,hi2;
                unpk(acc2[pp][f2][0], lo0, hi0);
                unpk(acc2[pp][f2][1], lo1, hi1);
                unpk(acc2[pp][f2][2], lo2, hi2);
                float ml = fmaxf(fmaxf(lo0,lo1),lo2);
                float mh = fmaxf(fmaxf(hi0,hi1),hi2);
                size_t base = ((size_t)((b*32+co0+2*pp)*5+f2))*TT + t0 + tl;
                g_s2[base]        = fmaxf(ml, 0.f);
                g_s2[base + 5*TT] = fmaxf(mh, 0.f);
            }
    }
}

// ============ stage 3: causal conv + maxpool3 + relu (FFMA2, co-pairs) ============
__global__ void __launch_bounds__(512) k_s3(const float* __restrict__ w3, const float* __restrict__ b3){
    extern __shared__ float sm[];
    float* s2s = sm;              // [160][132]
    float* w3s = sm + 160*132;    // 18432
    int tid = threadIdx.x, b = blockIdx.y, t0 = blockIdx.x*128;
    for (int i=tid; i<160*132; i+=512){
        int tl = i % 132, fr = i / 132;
        int tg = t0 + tl;
        s2s[i] = (tg < TT && tl < 130) ? g_s2[((size_t)(b*160+fr))*TT + tg] : 0.f;
    }
    for (int i=tid; i<18432; i+=512){
        int co = i & 63, r = i >> 6;
        int k = r % 3; r /= 3;
        int cin = r & 31, ii = r >> 5;
        w3s[i] = w3[((size_t)(ii*64+co)*32+cin)*3 + k];
    }
    __syncthreads();
    int co0 = (tid & 31)*2, tg8 = tid >> 5;
    float b0l=__ldg(b3+co0),     b0h=__ldg(b3+co0+1);
    float b1l=__ldg(b3+64+co0),  b1h=__ldg(b3+64+co0+1);
    float b2l=__ldg(b3+128+co0), b2h=__ldg(b3+128+co0+1);
    for (int chunk=0; chunk<2; chunk++){
        int tlbase = tg8*8 + chunk*4;
        unsigned long long acc2[4][3];
        #pragma unroll
        for (int rr=0;rr<4;rr++){ acc2[rr][0]=0ull; acc2[rr][1]=0ull; acc2[rr][2]=0ull; }
        for (int cin=0; cin<32; cin++){
            float sv[5][6];
            #pragma unroll
            for (int ff=0; ff<5; ff++){
                const float* p = s2s + (cin*5+ff)*132 + tlbase;
                float4 u0 = *(const float4*)p;
                float2 u1 = *(const float2*)(p+4);
                sv[ff][0]=u0.x; sv[ff][1]=u0.y; sv[ff][2]=u0.z; sv[ff][3]=u0.w;
                sv[ff][4]=u1.x; sv[ff][5]=u1.y;
            }
            #pragma unroll
            for (int ii=0; ii<3; ii++)
                #pragma unroll
                for (int k=0; k<3; k++){
                    unsigned long long wk2 =
                        *(const unsigned long long*)(w3s + ((ii*32+cin)*3+k)*64 + co0);
                    #pragma unroll
                    for (int f=0; f<3; f++){
                        int ff = f + k;
                        #pragma unroll
                        for (int rr=0; rr<4; rr++){
                            unsigned long long sb = pk2(sv[ff][rr+ii], sv[ff][rr+ii]);
                            acc2[rr][f] = ffma2(wk2, sb, acc2[rr][f]);
                        }
                    }
                }
        }
        #pragma unroll
        for (int rr=0; rr<4; rr++){
            int tg = t0 + tlbase + rr;
            float l0,h0,l1,h1,l2,h2;
            unpk(acc2[rr][0], l0, h0);
            unpk(acc2[rr][1], l1, h1);
            unpk(acc2[rr][2], l2, h2);
            float a0l=l0+b0l, a1l=l1+b0l, a2l=l2+b0l;
            float a0h=h0+b0h, a1h=h1+b0h, a2h=h2+b0h;
            if (tg+1 < TT){ a0l+=b1l; a1l+=b1l; a2l+=b1l; a0h+=b1h; a1h+=b1h; a2h+=b1h; }
            if (tg+2 < TT){ a0l+=b2l; a1l+=b2l; a2l+=b2l; a0h+=b2h; a1h+=b2h; a2h+=b2h; }
            float2 v;
            v.x = fmaxf(fmaxf(fmaxf(a0l,a1l),a2l), 0.f);
            v.y = fmaxf(fmaxf(fmaxf(a0h,a1h),a2h), 0.f);
            *(float2*)(g_x + ((size_t)(b*TT+tg))*64 + co0) = v;
        }
    }
}

// ============ LN1 + QKV via 3xBF16 mma, ldmatrix + frag-major B ============
__global__ void __launch_bounds__(1024) k_qkv(
        const float* __restrict__ Wq, const float* __restrict__ bq,
        const float* __restrict__ Wk, const float* __restrict__ bk,
        const float* __restrict__ Wv, const float* __restrict__ bv,
        const float* __restrict__ gam, const float* __restrict__ bet){
    extern __shared__ char smraw[];
    uint32_t* Whf = (uint32_t*)smraw;       // 6144
    uint32_t* Wlf = Whf + 6144;             // 6144
    uint32_t* Hh  = Wlf + 6144;             // 4608
    uint32_t* Hl  = Hh + 4608;              // 4608
    float*    bs  = (float*)(Hl + 4608);    // 192
    int tid = threadIdx.x;

    for (int i=tid; i<6144; i+=1024){
        int kp = i & 31, c = i >> 5;
        int seg = c >> 6, cl = c & 63;
        const float* Wsrc = (seg==0) ? Wq : (seg==1) ? Wk : Wv;
        float w0 = Wsrc[cl*64 + 2*kp], w1 = Wsrc[cl*64 + 2*kp + 1];
        int kpl = kp & 7, kt = kp >> 3;
        int idx = kt*1536 + c*8 + (kpl&3)*2 + (kpl>>2);
        Whf[idx] = pk_hi(w0, w1);
        Wlf[idx] = pk_lo(w0, w1);
    }
    if (tid < 64){ bs[tid]=bq[tid]; bs[64+tid]=bk[tid]; bs[128+tid]=bv[tid]; }

    {
        int tok = tid >> 3, lane8 = tid & 7;
        int gtok = blockIdx.x*128 + tok;
        const float* xr = g_x + (size_t)gtok*64 + lane8*8;
        float4 u0 = *(const float4*)xr, u1 = *(const float4*)(xr+4);
        float v[8] = {u0.x,u0.y,u0.z,u0.w,u1.x,u1.y,u1.z,u1.w};
        float s=0.f, ss=0.f;
        #pragma unroll
        for (int m=0;m<8;m++){ s += v[m]; ss += v[m]*v[m]; }
        s += __shfl_xor_sync(0xffffffffu,s,1); ss += __shfl_xor_sync(0xffffffffu,ss,1);
        s += __shfl_xor_sync(0xffffffffu,s,2); ss += __shfl_xor_sync(0xffffffffu,ss,2);
        s += __shfl_xor_sync(0xffffffffu,s,4); ss += __shfl_xor_sync(0xffffffffu,ss,4);
        float mean = s*(1.f/64.f);
        float var  = ss*(1.f/64.f) - mean*mean;
        float rstd = rsqrtf(fmaxf(var,0.f) + 1e-5f);
        float h[8];
        #pragma unroll
        for (int m=0;m<8;m++){
            int dd = lane8*8+m;
            h[m] = (v[m]-mean)*rstd*__ldg(gam+dd) + __ldg(bet+dd);
        }
        #pragma unroll
        for (int j=0;j<4;j++){
            Hh[tok*36 + lane8*4 + j] = pk_hi(h[2*j], h[2*j+1]);
            Hl[tok*36 + lane8*4 + j] = pk_lo(h[2*j], h[2*j+1]);
        }
    }
    __syncthreads();

    int lane = tid & 31, w = tid >> 5;
    int m0 = (w >> 2) << 4;
    int n0 = (w & 3) * 48;
    float acc[6][4];
    #pragma unroll
    for (int nt=0;nt<6;nt++){ acc[nt][0]=0.f; acc[nt][1]=0.f; acc[nt][2]=0.f; acc[nt][3]=0.f; }
    int row = m0 + (lane>>2);
    int arow = m0 + (lane & 7) + ((lane >> 3) & 1)*8;
    int acolx = ((lane >> 4) & 1)*4;
    #pragma unroll
    for (int kt=0; kt<4; kt++){
        uint32_t ah0,ah1,ah2,ah3, al0,al1,al2,al3;
        ldm4(ah0,ah1,ah2,ah3, Hh + arow*36 + kt*8 + acolx);
        ldm4(al0,al1,al2,al3, Hl + arow*36 + kt*8 + acolx);
        int bbase = kt*1536 + (n0 + (lane>>2))*8 + (lane&3)*2;
        #pragma unroll
        for (int nt=0; nt<6; nt++){
            uint2 bh = *(const uint2*)(Whf + bbase + nt*64);
            uint2 bl = *(const uint2*)(Wlf + bbase + nt*64);
            MMA_BF16(acc[nt], al0,al1,al2,al3, bh.x,bh.y);
            MMA_BF16(acc[nt], ah0,ah1,ah2,ah3, bl.x,bl.y);
            MMA_BF16(acc[nt], ah0,ah1,ah2,ah3, bh.x,bh.y);
        }
    }
    int gt = blockIdx.x*128 + row;
    #pragma unroll
    for (int nt=0; nt<6; nt++){
        int colg = n0 + nt*8 + 2*(lane&3);
        int seg = colg >> 6, cl = colg & 63;
        float* dst = (seg==0) ? g_q : (seg==1) ? g_k : g_v;
        float b0 = bs[colg], b1 = bs[colg+1];
        float2 v0; v0.x = acc[nt][0] + b0; v0.y = acc[nt][1] + b1;
        *(float2*)(dst + (size_t)gt*64 + cl) = v0;
        float2 v1; v1.x = acc[nt][2] + b0; v1.y = acc[nt][3] + b1;
        *(float2*)(dst + (size_t)(gt+8)*64 + cl) = v1;
    }
}

// ============ attention + residual + LN2 + FF(3xBF16 mma) + residual ============
__global__ void __launch_bounds__(512, 2) k_attnff(
        const float* __restrict__ Er, int shift,
        const float* __restrict__ W1g, const float* __restrict__ b1p,
        const float* __restrict__ W2g, const float* __restrict__ b2p,
        const float* __restrict__ gam, const float* __restrict__ bet){
    extern __shared__ char smraw[];
    uint32_t* W1hf = (uint32_t*)smraw;       // 2048
    uint32_t* W1lf = W1hf + 2048;
    uint32_t* W2hf = W1lf + 2048;
    uint32_t* W2lf = W2hf + 2048;
    uint32_t* hsh  = W2lf + 2048;            // 2304
    uint32_t* hsl  = hsh + 2304;
    float*    xs   = (float*)(hsl + 2304);   // 4352
    float*    bs   = xs + 4352;              // 128
    float*    ers  = bs + 128;               // 400 (8 heads x pitch 50)
    int tid = threadIdx.x;

    for (int i=tid; i<2048; i+=512){
        int kp = i & 31, c = i >> 5;
        int kpl = kp & 7, kt = kp >> 3;
        int idx = kt*512 + c*8 + (kpl&3)*2 + (kpl>>2);
        float w0 = W1g[c*64 + 2*kp], w1 = W1g[c*64 + 2*kp + 1];
        W1hf[idx] = pk_hi(w0, w1);
        W1lf[idx] = pk_lo(w0, w1);
        w0 = W2g[c*64 + 2*kp]; w1 = W2g[c*64 + 2*kp + 1];
        W2hf[idx] = pk_hi(w0, w1);
        W2lf[idx] = pk_lo(w0, w1);
    }
    if (tid < 64){ bs[tid]=b1p[tid]; bs[64+tid]=b2p[tid]; }
    if (tid < 384){ int h = tid/48, c = tid%48; ers[h*50 + c] = Er[tid]; }
    __syncthreads();

    // ---- attention: 8 threads/token, 1 head each ----
    {
        int tok = tid >> 3, h = tid & 7;
        int gtok = blockIdx.x*64 + tok;
        int b = gtok >> 12, t = gtok & (TT-1);
        size_t bt = (size_t)b*TT + t;
        int sh[6]; sh[0]=0; sh[1]=0; sh[2]=shift; sh[3]=2*shift; sh[4]=3*shift; sh[5]=4*shift;
        const float* qp = g_q + bt*64 + h*8;
        float4 q0 = *(const float4*)qp, q1 = *(const float4*)(qp+4);
        float q[8] = {q0.x,q0.y,q0.z,q0.w,q1.x,q1.y,q1.z,q1.w};
        const float* er = ers + h*50;
        float lg[6];
        #pragma unroll
        for (int j=0;j<6;j++){
            float qe = 0.f;
            #pragma unroll
            for (int d=0;d<8;d++) qe += q[d]*er[d*6 + j];
            lg[j] = qe;
        }
        #pragma unroll
        for (int j=0;j<6;j++){
            int tp = t - sh[j];
            float qk = 0.f;
            if (tp >= 0){
                const float* kp = g_k + ((size_t)b*TT+tp)*64 + h*8;
                float4 k0 = *(const float4*)kp, k1 = *(const float4*)(kp+4);
                qk = q[0]*k0.x + q[1]*k0.y + q[2]*k0.z + q[3]*k0.w
                   + q[4]*k1.x + q[5]*k1.y + q[6]*k1.z + q[7]*k1.w;
            }
            lg[j] = (qk + lg[j]) * 0.3535533905932738f;
        }
        float mx = lg[0];
        #pragma unroll
        for (int j=1;j<6;j++) mx = fmaxf(mx, lg[j]);
        float e[6], se = 0.f;
        #pragma unroll
        for (int j=0;j<6;j++){ e[j] = __expf(lg[j]-mx); se += e[j]; }
        float inv = 1.f/se;
        float o[8] = {0,0,0,0,0,0,0,0};
        #pragma unroll
        for (int j=0;j<6;j++){
            int tp = t - sh[j];
            if (tp >= 0){
                const float* vp = g_v + ((size_t)b*TT+tp)*64 + h*8;
                float4 v0 = *(const float4*)vp, v1 = *(const float4*)(vp+4);
                float a = e[j];
                o[0]+=a*v0.x; o[1]+=a*v0.y; o[2]+=a*v0.z; o[3]+=a*v0.w;
                o[4]+=a*v1.x; o[5]+=a*v1.y; o[6]+=a*v1.z; o[7]+=a*v1.w;
            }
        }
        const float* xp = g_x + (size_t)gtok*64 + h*8;
        float4 x0 = *(const float4*)xp, x1 = *(const float4*)(xp+4);
        float* xd = xs + tok*68 + h*8;
        xd[0]=x0.x+o[0]*inv; xd[1]=x0.y+o[1]*inv; xd[2]=x0.z+o[2]*inv; xd[3]=x0.w+o[3]*inv;
        xd[4]=x1.x+o[4]*inv; xd[5]=x1.y+o[5]*inv; xd[6]=x1.z+o[6]*inv; xd[7]=x1.w+o[7]*inv;
    }
    __syncthreads();

    {
        int tok = tid >> 3, lane8 = tid & 7;
        float v[8];
        #pragma unroll
        for (int m=0;m<8;m++) v[m] = xs[tok*68 + lane8*8 + m];
        float s=0.f, ss=0.f;
        #pragma unroll
        for (int m=0;m<8;m++){ s += v[m]; ss += v[m]*v[m]; }
        s += __shfl_xor_sync(0xffffffffu,s,1); ss += __shfl_xor_sync(0xffffffffu,ss,1);
        s += __shfl_xor_sync(0xffffffffu,s,2); ss += __shfl_xor_sync(0xffffffffu,ss,2);
        s += __shfl_xor_sync(0xffffffffu,s,4); ss += __shfl_xor_sync(0xffffffffu,ss,4);
        float mean = s*(1.f/64.f);
        float var  = ss*(1.f/64.f) - mean*mean;
        float rstd = rsqrtf(fmaxf(var,0.f) + 1e-5f);
        float h[8];
        #pragma unroll
        for (int m=0;m<8;m++){
            int dd = lane8*8+m;
            h[m] = (v[m]-mean)*rstd*__ldg(gam+dd) + __ldg(bet+dd);
        }
        #pragma unroll
        for (int j=0;j<4;j++){
            hsh[tok*36 + lane8*4 + j] = pk_hi(h[2*j], h[2*j+1]);
            hsl[tok*36 + lane8*4 + j] = pk_lo(h[2*j], h[2*j+1]);
        }
    }
    __syncthreads();

    int lane = tid & 31, w = tid >> 5;
    int m0 = (w >> 2) << 4;
    int n0 = (w & 3) * 16;
    int row = m0 + (lane>>2);
    int arow = m0 + (lane & 7) + ((lane >> 3) & 1)*8;
    int acolx = ((lane >> 4) & 1)*4;

    float acc[2][4];
    #pragma unroll
    for (int nt=0;nt<2;nt++){ acc[nt][0]=0.f; acc[nt][1]=0.f; acc[nt][2]=0.f; acc[nt][3]=0.f; }
    #pragma unroll
    for (int kt=0; kt<4; kt++){
        uint32_t ah0,ah1,ah2,ah3, al0,al1,al2,al3;
        ldm4(ah0,ah1,ah2,ah3, hsh + arow*36 + kt*8 + acolx);
        ldm4(al0,al1,al2,al3, hsl + arow*36 + kt*8 + acolx);
        int bbase = kt*512 + (n0 + (lane>>2))*8 + (lane&3)*2;
        #pragma unroll
        for (int nt=0; nt<2; nt++){
            uint2 bh = *(const uint2*)(W1hf + bbase + nt*64);
            uint2 bl = *(const uint2*)(W1lf + bbase + nt*64);
            MMA_BF16(acc[nt], al0,al1,al2,al3, bh.x,bh.y);
            MMA_BF16(acc[nt], ah0,ah1,ah2,ah3, bl.x,bl.y);
            MMA_BF16(acc[nt], ah0,ah1,ah2,ah3, bh.x,bh.y);
        }
    }
    __syncthreads();
    #pragma unroll
    for (int nt=0; nt<2; nt++){
        int colg = n0 + nt*8 + 2*(lane&3);
        int kp = (colg >> 1);
        float bb0 = bs[colg], bb1 = bs[colg+1];
        float z0 = acc[nt][0] + bb0; z0 = 0.5f*z0*(1.f + erff(z0*0.7071067811865475f));
        float z1 = acc[nt][1] + bb1; z1 = 0.5f*z1*(1.f + erff(z1*0.7071067811865475f));
        hsh[row*36 + kp] = pk_hi(z0, z1);
        hsl[row*36 + kp] = pk_lo(z0, z1);
        float z2 = acc[nt][2] + bb0; z2 = 0.5f*z2*(1.f + erff(z2*0.7071067811865475f));
        float z3 = acc[nt][3] + bb1; z3 = 0.5f*z3*(1.f + erff(z3*0.7071067811865475f));
        hsh[(row+8)*36 + kp] = pk_hi(z2, z3);
        hsl[(row+8)*36 + kp] = pk_lo(z2, z3);
    }
    __syncthreads();

    float acc2[2][4];
    #pragma unroll
    for (int nt=0;nt<2;nt++){ acc2[nt][0]=0.f; acc2[nt][1]=0.f; acc2[nt][2]=0.f; acc2[nt][3]=0.f; }
    #pragma unroll
    for (int kt=0; kt<4; kt++){
        uint32_t ah0,ah1,ah2,ah3, al0,al1,al2,al3;
        ldm4(ah0,ah1,ah2,ah3, hsh + arow*36 + kt*8 + acolx);
        ldm4(al0,al1,al2,al3, hsl + arow*36 + kt*8 + acolx);
        int bbase = kt*512 + (n0 + (lane>>2))*8 + (lane&3)*2;
        #pragma unroll
        for (int nt=0; nt<2; nt++){
            uint2 bh = *(const uint2*)(W2hf + bbase + nt*64);
            uint2 bl = *(const uint2*)(W2lf + bbase + nt*64);
            MMA_BF16(acc2[nt], al0,al1,al2,al3, bh.x,bh.y);
            MMA_BF16(acc2[nt], ah0,ah1,ah2,ah3, bl.x,bl.y);
            MMA_BF16(acc2[nt], ah0,ah1,ah2,ah3, bh.x,bh.y);
        }
    }
    int gt = blockIdx.x*64 + row;
    #pragma unroll
    for (int nt=0; nt<2; nt++){
        int colg = n0 + nt*8 + 2*(lane&3);
        float bb0 = bs[64+colg], bb1 = bs[64+colg+1];
        float2 v0;
        v0.x = xs[row*68 + colg]     + acc2[nt][0] + bb0;
        v0.y = xs[row*68 + colg + 1] + acc2[nt][1] + bb1;
        *(float2*)(g_x + (size_t)gt*64 + colg) = v0;
        float2 v1;
        v1.x = xs[(row+8)*68 + colg]     + acc2[nt][2] + bb0;
        v1.y = xs[(row+8)*68 + colg + 1] + acc2[nt][3] + bb1;
        *(float2*)(g_x + (size_t)(gt+8)*64 + colg) = v1;
    }
}

// ============ 1x1 conv out + sigmoid ============
__global__ void k_out(const float* __restrict__ ow, const float* __restrict__ ob,
                      float* __restrict__ out){
    int id = blockIdx.x*256 + threadIdx.x;
    int t = id & (TT-1), b = id >> 12;
    const float4* xp = (const float4*)(g_x + (size_t)id*64);
    float a0 = __ldg(ob), a1 = __ldg(ob+1);
    #pragma unroll
    for (int d4=0; d4<16; d4++){
        float4 xv = xp[d4];
        a0 += xv.x*__ldg(ow+d4*4) + xv.y*__ldg(ow+d4*4+1) + xv.z*__ldg(ow+d4*4+2) + xv.w*__ldg(ow+d4*4+3);
        a1 += xv.x*__ldg(ow+64+d4*4) + xv.y*__ldg(ow+64+d4*4+1) + xv.z*__ldg(ow+64+d4*4+2) + xv.w*__ldg(ow+64+d4*4+3);
    }
    out[((size_t)(b*2))*TT + t]   = 1.f/(1.f+expf(-a0));
    out[((size_t)(b*2+1))*TT + t] = 1.f/(1.f+expf(-a1));
}

extern "C" void kernel_launch(void* const* d_in, const int* in_sizes, int n_in,
                              void* d_out, int out_size){
    const float* spec = (const float*)d_in[0];
    const float* c1w = (const float*)d_in[1];
    const float* c1b = (const float*)d_in[2];
    const float* c2w = (const float*)d_in[3];
    const float* c2b = (const float*)d_in[4];
    const float* c3w = (const float*)d_in[5];
    const float* c3b = (const float*)d_in[6];
    const float* Wq  = (const float*)d_in[7];
    const float* bq  = (const float*)d_in[8];
    const float* Wk  = (const float*)d_in[9];
    const float* bk  = (const float*)d_in[10];
    const float* Wv  = (const float*)d_in[11];
    const float* bv  = (const float*)d_in[12];
    const float* Er  = (const float*)d_in[13];
    const float* g1  = (const float*)d_in[14];
    const float* be1 = (const float*)d_in[15];
    const float* W1  = (const float*)d_in[16];
    const float* b1  = (const float*)d_in[17];
    const float* W2  = (const float*)d_in[18];
    const float* b2  = (const float*)d_in[19];
    const float* g2  = (const float*)d_in[20];
    const float* be2 = (const float*)d_in[21];
    const float* ow  = (const float*)d_in[22];
    const float* ob  = (const float*)d_in[23];

    const int SM_QKV    = (6144*2 + 4608*2)*4 + 192*4;               // 86784
    const int SM_ATTNFF = (2048*4 + 2304*2)*4 + (4352+128+400)*4;    // 70656

    cudaFuncSetAttribute(k_s2,  cudaFuncAttributeMaxDynamicSharedMemorySize, 65536);
    cudaFuncSetAttribute(k_s3,  cudaFuncAttributeMaxDynamicSharedMemorySize, 158208);
    cudaFuncSetAttribute(k_qkv, cudaFuncAttributeMaxDynamicSharedMemorySize, SM_QKV);
    cudaFuncSetAttribute(k_attnff, cudaFuncAttributeMaxDynamicSharedMemorySize, SM_ATTNFF);

    k_s1<<<3328, 256>>>(spec, c1w, c1b);
    k_s2<<<dim3(64,8), 256, 65536>>>(c2w, c2b);
    k_s3<<<dim3(32,8), 512, 158208>>>(c3w, c3b);
    for (int L=0; L<11; L++){
        k_qkv<<<256, 1024, SM_QKV>>>(Wq+L*4096, bq+L*64, Wk+L*4096, bk+L*64,
                                     Wv+L*4096, bv+L*64, g1+L*64, be1+L*64);
        k_attnff<<<512, 512, SM_ATTNFF>>>(Er+L*384, 1<<L,
                                          W1+L*4096, b1+L*64, W2+L*4096, b2+L*64,
                                          g2+L*64, be2+L*64);
    }
    k_out<<<128, 256>>>(ow, ob, (float*)d_out);
}